// round 11
// baseline (speedup 1.0000x reference)
#include <cuda_runtime.h>

#define Nn 4096
#define Dd 128
#define H1h 256

typedef unsigned long long u64;

// ---------------- device scratch (all matrices 128B-aligned) ----------------
__device__ __align__(128) float g_Wt [Dd*Dd];
__device__ __align__(128) float g_M  [Dd*Dd];
__device__ __align__(128) float g_P2[Dd*Dd],  g_P3[Dd*Dd],  g_P4[Dd*Dd],  g_P7[Dd*Dd];
__device__ __align__(128) float g_P8[Dd*Dd],  g_P15[Dd*Dd], g_P16[Dd*Dd], g_P31[Dd*Dd];
__device__ __align__(128) float g_P32[Dd*Dd], g_P63[Dd*Dd], g_P64[Dd*Dd], g_P127[Dd*Dd];
__device__ __align__(128) float g_ET [Dd*Dd];
__device__ float g_s2[H1h];
__device__ float g_B2;
__device__ float g_regP[128];
__device__ __align__(128) float g_y [Nn*Dd];
__device__ float g_T [Dd*256];
__device__ float g_Pa[Dd*257];
__device__ float g_Pb[Dd*257];

// ladder level tables: [lv*2 + product]
__device__ float* const g_lvlL[14] = {g_M,g_M,  g_M,g_P2,  g_P3,g_P4,  g_P7,g_P8,
                                      g_P15,g_P16, g_P31,g_P32, g_P63,g_P63};
__device__ float* const g_lvlR[14] = {g_M,g_M,  g_P2,g_P2, g_P4,g_P4,  g_P8,g_P8,
                                      g_P16,g_P16, g_P32,g_P32, g_P64,g_P64};
__device__ float* const g_lvlD[14] = {g_P2,g_P2, g_P3,g_P4, g_P7,g_P8,  g_P15,g_P16,
                                      g_P31,g_P32, g_P63,g_P64, g_P127,g_P127};
__device__ const int g_lvl2[7] = {0,1,1,1,1,1,0};

// -------- tree grid barrier (128 blocks; 16 leaves x 8 + root) --------------
__device__ volatile unsigned g_gen = 0;
__device__ unsigned g_leaf[16*32];
__device__ unsigned g_root = 0;

__device__ __forceinline__ void gridbar(){
    __syncthreads();
    if (threadIdx.x == 0){
        __threadfence();
        unsigned g = g_gen;
        unsigned leaf = blockIdx.x & 15;
        if (atomicAdd(&g_leaf[leaf*32], 1u) == 7u){
            g_leaf[leaf*32] = 0;
            __threadfence();
            if (atomicAdd(&g_root, 1u) == 15u){
                g_root = 0;
                __threadfence();
                g_gen = g + 1;
            }
        }
        int n = 0;
        while (g_gen == g){ if (++n > 32) __nanosleep(64); }
    }
    __syncthreads();
}

// ---------------- helpers ----------------------------------------------------
__device__ __forceinline__ void upk2(u64 v, float& lo, float& hi){
    asm("mov.b64 {%0, %1}, %2;" : "=f"(lo), "=f"(hi) : "l"(v));
}
__device__ __forceinline__ u64 fma2(u64 a, u64 b, u64 c){
    u64 d; asm("fma.rn.f32x2 %0, %1, %2, %3;" : "=l"(d) : "l"(a), "l"(b), "l"(c));
    return d;
}
__device__ __forceinline__ void touch4(const float4* p){
    float a, b, c, d;
    asm volatile("ld.global.ca.v4.f32 {%0,%1,%2,%3}, [%4];"
                 : "=f"(a), "=f"(b), "=f"(c), "=f"(d) : "l"(p));
}

// ======== kernel 1: prep (distributed) + fsetup, fused (128 blocks) =========
__global__ void __launch_bounds__(256, 1)
prepsetup_kernel(const float* __restrict__ weight,
                 const float* __restrict__ A,
                 const float* __restrict__ W2,
                 const float* __restrict__ b2,
                 const float* __restrict__ W1,
                 const float* __restrict__ b1,
                 float* __restrict__ d_out)
{
    __shared__ float red[256];
    __shared__ float key[256]; __shared__ int sidx[256];
    __shared__ float asA[256], bsA[256];
    __shared__ int   upA[256];
    __shared__ float UA[256], UB[256], DA[256], DB[256];

    int t = threadIdx.x, b = blockIdx.x;
    float labs = 0.f;
    if (t < 128){
        int idx = b*128 + t;
        float w = weight[idx] * A[idx];
        int r = idx >> 7, c = idx & 127;
        g_Wt[c*Dd + r] = w;
        g_M[idx] = (r == c ? 1.f : 0.f) + (w*w)*(1.f/128.f);
        labs = fabsf(w);
    }
    {
        int w = t >> 5, lane = t & 31;
        if (w < 2){
            int row = b*2 + w;
            const float* p = W2 + row*128;
            float v = (p[lane] + p[lane+32]) + (p[lane+64] + p[lane+96]);
            #pragma unroll
            for (int s = 16; s > 0; s >>= 1)
                v += __shfl_xor_sync(0xffffffffu, v, s);
            if (lane == 0) g_s2[row] = v;
        }
    }
    if (b == 0){
        red[t] = (t < 128) ? b2[t] : 0.f;
        __syncthreads();
        for (int s = 128; s > 0; s >>= 1){
            if (t < s) red[t] += red[t + s];
            __syncthreads();
        }
        if (t == 0) g_B2 = red[0];
        __syncthreads();
    }
    red[t] = labs;
    __syncthreads();
    for (int s = 128; s > 0; s >>= 1){
        if (t < s) red[t] += red[t + s];
        __syncthreads();
    }
    if (t == 0) g_regP[b] = red[0];
    gridbar();
    if (b == 0){
        red[t] = (t < 128) ? g_regP[t] : 0.f;
        __syncthreads();
        for (int s = 128; s > 0; s >>= 1){
            if (t < s) red[t] += red[t + s];
            __syncthreads();
        }
        if (t == 0) d_out[Nn*Dd + 1] = red[0];
    }
    __syncthreads();

    // ---- fsetup: block b handles column i = b ----
    int i = b;
    float a = W1[i*H1h + t];
    float bb = b1[t];
    float s = __ldcg(&g_s2[t]);
    float as = a*s, bs = bb*s;
    float tb; int up; float c0 = 0.f;
    if (a > 0.f)      { tb = -bb/a; up = 1; }
    else if (a < 0.f) { tb = -bb/a; up = 0; }
    else { tb = __int_as_float(0x7f800000); up = 1; as = 0.f; bs = 0.f;
           c0 = fmaxf(bb, 0.f) * s; }

    key[t] = tb; sidx[t] = t;
    asA[t] = as; bsA[t] = bs; upA[t] = up;
    __syncthreads();

    for (int ksz = 2; ksz <= 256; ksz <<= 1){
        for (int jsz = ksz >> 1; jsz > 0; jsz >>= 1){
            int ixj = t ^ jsz;
            float k0 = key[t], k1 = key[ixj];
            int   i0 = sidx[t], i1 = sidx[ixj];
            __syncthreads();
            if (ixj > t){
                bool asc = ((t & ksz) == 0);
                bool sw  = asc ? (k0 > k1) : (k0 < k1);
                if (sw){ key[t] = k1; key[ixj] = k0;
                         sidx[t] = i1; sidx[ixj] = i0; }
            }
            __syncthreads();
        }
    }

    int o = sidx[t];
    float pas = asA[o], pbs = bsA[o];
    int pup = upA[o];
    UA[t] = pup ? pas : 0.f;  UB[t] = pup ? pbs : 0.f;
    DA[t] = pup ? 0.f : pas;  DB[t] = pup ? 0.f : pbs;
    __syncthreads();

    for (int off = 1; off < 256; off <<= 1){
        float ua = (t >= off) ? UA[t-off] : 0.f;
        float ub = (t >= off) ? UB[t-off] : 0.f;
        float da = (t >= off) ? DA[t-off] : 0.f;
        float db = (t >= off) ? DB[t-off] : 0.f;
        __syncthreads();
        UA[t] += ua; UB[t] += ub; DA[t] += da; DB[t] += db;
        __syncthreads();
    }

    red[t] = c0;
    __syncthreads();
    for (int st = 128; st > 0; st >>= 1){
        if (t < st) red[t] += red[t + st];
        __syncthreads();
    }
    float C0 = red[0] + __ldcg(&g_B2);
    float totDA = DA[255], totDB = DB[255];

    float exUA = (t > 0) ? UA[t-1] : 0.f;
    float exUB = (t > 0) ? UB[t-1] : 0.f;
    float exDA = (t > 0) ? DA[t-1] : 0.f;
    float exDB = (t > 0) ? DB[t-1] : 0.f;

    g_T [i*256 + t] = key[t];
    g_Pa[i*257 + t] = exUA + (totDA - exDA);
    g_Pb[i*257 + t] = exUB + (totDB - exDB) + C0;
    if (t == 255){
        g_Pa[i*257 + 256] = UA[255];
        g_Pb[i*257 + 256] = UB[255] + C0;
    }
}

// ======== kernel 2: gemm  y = x @ W + bias (128 blocks) =====================
__global__ void __launch_bounds__(256)
gemm_kernel(const float* __restrict__ x, const float* __restrict__ bias)
{
    __shared__ __align__(16) float xs[32*128];
    int t  = threadIdx.x;
    int n0 = blockIdx.x * 32;
    for (int idx = t; idx < 32*128; idx += 256)
        xs[idx] = x[n0*128 + idx];
    __syncthreads();

    int i  = t & 127;
    int ng = t >> 7;
    // 128-bit w loads; identical value packing (w01 = d2, w23 = d2+1)
    const ulonglong2* wrow2 = (const ulonglong2*)(g_Wt + i*128);
    u64 acc[16];
    #pragma unroll
    for (int u = 0; u < 16; u++) acc[u] = 0ULL;

    #pragma unroll 4
    for (int q = 0; q < 32; q++){                 // q = d2/2
        ulonglong2 wv = wrow2[q];
        u64 w01 = wv.x, w23 = wv.y;
        #pragma unroll
        for (int u = 0; u < 16; u++){
            const u64* xp = (const u64*)&xs[(ng*16 + u)*128 + q*4];
            acc[u] = fma2(xp[0], w01, acc[u]);
            acc[u] = fma2(xp[1], w23, acc[u]);
        }
    }
    float bi = bias[i];
    #pragma unroll
    for (int u = 0; u < 16; u++){
        float p, q; upk2(acc[u], p, q);
        g_y[(n0 + ng*16 + u)*Dd + i] = (p + q) + bi;
    }
}

// ======== kernel 3: feval (128 blocks, tables once, 4 n-tiles) ==============
#define FEVAL_I 8
__global__ void __launch_bounds__(256)
feval_kernel(float* __restrict__ d_out)
{
    extern __shared__ float dyn[];
    float* sT  = dyn;
    float* sPa = sT  + FEVAL_I*257;
    float* sPb = sPa + FEVAL_I*257;

    int t = threadIdx.x, bid = blockIdx.x;
    int i0 = (bid & 15) * FEVAL_I;

    for (int idx = t; idx < FEVAL_I*257; idx += 256){
        int ii = idx / 257, kk = idx - ii*257;
        sT [idx] = (kk < 256) ? g_T[(i0+ii)*256 + kk] : __int_as_float(0x7f800000);
        sPa[idx] = g_Pa[(i0+ii)*257 + kk];
        sPb[idx] = g_Pb[(i0+ii)*257 + kk];
    }
    __syncthreads();

    int li = t & 7, rg = t >> 3;
    const float* Tl  = sT  + li*257;
    const float* Pal = sPa + li*257;
    const float* Pbl = sPb + li*257;

    #pragma unroll
    for (int q = 0; q < 4; q++){
        int n0 = ((bid >> 4) + 8*q) * 128;
        float yv[4];
        int   kk[4];
        #pragma unroll
        for (int p = 0; p < 4; p++){
            yv[p] = g_y[(n0 + rg + p*32)*Dd + i0 + li];
            kk[p] = 0;
        }
        #pragma unroll
        for (int stp = 128; stp > 0; stp >>= 1){
            #pragma unroll
            for (int p = 0; p < 4; p++)
                if (Tl[kk[p] + stp - 1] < yv[p]) kk[p] += stp;
        }
        #pragma unroll
        for (int p = 0; p < 4; p++)
            d_out[(n0 + rg + p*32)*Dd + i0 + li]
                = fmaf(yv[p], Pal[kk[p]], Pbl[kk[p]]);
    }
}

// ======== kernel 4: ladder + transpose + hsum (128 blocks) ==================
__global__ void __launch_bounds__(256, 1)
ladder_kernel(float* __restrict__ d_out)
{
    __shared__ float Ls[256];
    int t = threadIdx.x, bid = blockIdx.x;
    int j = t & 127, h = t >> 7;

    for (int lv = 0; lv < 7; lv++){
        int two = g_lvl2[lv];
        int p   = two ? (bid >> 6)     : 0;
        int nr  = two ? 2              : 1;
        int rb  = two ? (bid & 63) * 2 : bid;
        const float* L  = g_lvlL[lv*2 + p];
        const float* R  = g_lvlR[lv*2 + p];
        float*       Dm = g_lvlD[lv*2 + p];

        // pretouch R (64KB) into this SM's L1
        for (int q = t; q < 4096; q += 256)
            touch4((const float4*)R + q);
        if (t < nr*128) Ls[t] = __ldcg(L + rb*128 + t);
        __syncthreads();
        if (h < nr){
            const float* Lr = Ls + h*128;
            const float* Rj = R + j;
            // ring-16: 64-cyc load->use lead >= 39-cyc L1-hit latency
            float buf[16];
            #pragma unroll
            for (int k = 0; k < 16; k++) buf[k] = Rj[k*128];
            float acc = 0.f;                       // single-acc ascending-k
            #pragma unroll
            for (int k = 0; k < 112; k++){
                float v = buf[k & 15];
                buf[k & 15] = Rj[(k+16)*128];
                acc = fmaf(Lr[k], v, acc);
            }
            #pragma unroll
            for (int k = 112; k < 128; k++)
                acc = fmaf(Lr[k], buf[k & 15], acc);
            Dm[(rb + h)*128 + j] = acc;
        }
        gridbar();
    }

    // transpose P127 -> ET (block b = column b)
    if (t < 128)
        g_ET[bid*128 + t] = __ldcg(&g_P127[t*128 + bid]);
    gridbar();

    // hsum: pretouch then identical 32-lane ascending FMA chain
    if (bid == 0){
        for (int q = t; q < 4096; q += 256){
            touch4((const float4*)g_ET + q);
            touch4((const float4*)g_M  + q);
        }
        __syncthreads();
        if (t < 32){
            __shared__ float pp[32];
            int l = t;
            float bufE[8], bufM[8];
            #pragma unroll
            for (int q = 0; q < 8; q++){
                int idx = l + (q << 5);
                bufE[q] = g_ET[idx];
                bufM[q] = g_M[idx];
            }
            float s = 0.f;
            for (int it = 0; it < 504; it++){
                float e = bufE[it & 7], m = bufM[it & 7];
                int idx = l + ((it + 8) << 5);
                bufE[it & 7] = g_ET[idx];
                bufM[it & 7] = g_M[idx];
                s = fmaf(e, m, s);
            }
            #pragma unroll
            for (int it = 504; it < 512; it++)
                s = fmaf(bufE[it & 7], bufM[it & 7], s);
            pp[l] = s;
            __syncwarp();
            for (int st = 16; st > 0; st >>= 1){
                if (l < st) pp[l] += pp[l + st];
                __syncwarp();
            }
            if (l == 0) d_out[Nn*Dd] = pp[0] - 128.f;
        }
    }
}

// ---------------- launch ------------------------------------------------------
extern "C" void kernel_launch(void* const* d_in, const int* in_sizes, int n_in,
                              void* d_out, int out_size)
{
    (void)in_sizes; (void)n_in; (void)out_size;
    const float* x      = (const float*)d_in[0];
    const float* weight = (const float*)d_in[1];
    const float* bias   = (const float*)d_in[2];
    const float* A      = (const float*)d_in[3];
    const float* W1     = (const float*)d_in[4];
    const float* b1     = (const float*)d_in[5];
    const float* W2     = (const float*)d_in[6];
    const float* b2     = (const float*)d_in[7];
    float* out = (float*)d_out;

    const int FEVAL_SMEM = 3*FEVAL_I*257*(int)sizeof(float);

    static bool attr_done = false;
    if (!attr_done){
        cudaFuncSetAttribute(feval_kernel,
                             cudaFuncAttributeMaxDynamicSharedMemorySize, FEVAL_SMEM);
        attr_done = true;
    }

    prepsetup_kernel<<<128, 256>>>(weight, A, W2, b2, W1, b1, out);
    gemm_kernel     <<<128, 256>>>(x, bias);
    feval_kernel    <<<128, 256, FEVAL_SMEM>>>(out);
    ladder_kernel   <<<128, 256>>>(out);
}

// round 12
// speedup vs baseline: 1.2824x; 1.2824x over previous
#include <cuda_runtime.h>

#define Nn 4096
#define Dd 128
#define H1h 256

typedef unsigned long long u64;

// ---------------- device scratch (all matrices 128B-aligned) ----------------
__device__ __align__(128) float g_Wt [Dd*Dd];
__device__ __align__(128) float g_M  [Dd*Dd];
__device__ __align__(128) float g_P2[Dd*Dd],  g_P3[Dd*Dd],  g_P4[Dd*Dd],  g_P7[Dd*Dd];
__device__ __align__(128) float g_P8[Dd*Dd],  g_P15[Dd*Dd], g_P16[Dd*Dd], g_P31[Dd*Dd];
__device__ __align__(128) float g_P32[Dd*Dd], g_P63[Dd*Dd], g_P64[Dd*Dd], g_P127[Dd*Dd];
__device__ __align__(128) float g_ET [Dd*Dd];
__device__ float g_s2[H1h];
__device__ float g_B2;
__device__ float g_regP[128];
__device__ __align__(128) float g_y [Nn*Dd];
__device__ float g_T [Dd*256];
__device__ float g_Pa[Dd*257];
__device__ float g_Pb[Dd*257];

// ladder level tables: [lv*2 + product]
__device__ float* const g_lvlL[14] = {g_M,g_M,  g_M,g_P2,  g_P3,g_P4,  g_P7,g_P8,
                                      g_P15,g_P16, g_P31,g_P32, g_P63,g_P63};
__device__ float* const g_lvlR[14] = {g_M,g_M,  g_P2,g_P2, g_P4,g_P4,  g_P8,g_P8,
                                      g_P16,g_P16, g_P32,g_P32, g_P64,g_P64};
__device__ float* const g_lvlD[14] = {g_P2,g_P2, g_P3,g_P4, g_P7,g_P8,  g_P15,g_P16,
                                      g_P31,g_P32, g_P63,g_P64, g_P127,g_P127};
__device__ const int g_lvl2[7] = {0,1,1,1,1,1,0};

// -------- hybrid cluster/global barrier state -------------------------------
__device__ volatile unsigned g_gen = 0;
__device__ unsigned g_leaf[8*32];    // 8 leaf counters, one per 128B line
__device__ unsigned g_root = 0;

#define CLUSTER_ARRIVE() asm volatile("barrier.cluster.arrive.aligned;" ::: "memory")
#define CLUSTER_WAIT()   asm volatile("barrier.cluster.wait.aligned;"   ::: "memory")

__device__ __forceinline__ unsigned cluster_rank(){
    unsigned r; asm("mov.u32 %0, %%cluster_ctarank;" : "=r"(r)); return r;
}

// Hybrid barrier: HW cluster barrier pairs CTAs; 64 leaders do an 8-leaf
// tree of atomics; release via one volatile word polled with ALU backoff.
__device__ __forceinline__ unsigned gridbar_c(unsigned gen){
    CLUSTER_ARRIVE(); CLUSTER_WAIT();
    if (threadIdx.x == 0 && cluster_rank() == 0){
        __threadfence();
        unsigned leaf = (blockIdx.x >> 1) & 7;          // 64 leaders -> 8 leaves
        if (atomicAdd(&g_leaf[leaf*32], 1u) == 7u){
            g_leaf[leaf*32] = 0;
            __threadfence();
            if (atomicAdd(&g_root, 1u) == 7u){
                g_root = 0;
                __threadfence();
                g_gen = gen + 1;
            }
        }
        while (g_gen != gen + 1){
            #pragma unroll
            for (int q = 0; q < 48; q++) asm volatile("");
        }
    }
    CLUSTER_ARRIVE(); CLUSTER_WAIT();
    return gen + 1;
}

// ---------------- helpers ----------------------------------------------------
__device__ __forceinline__ void upk2(u64 v, float& lo, float& hi){
    asm("mov.b64 {%0, %1}, %2;" : "=f"(lo), "=f"(hi) : "l"(v));
}
__device__ __forceinline__ u64 fma2(u64 a, u64 b, u64 c){
    u64 d; asm("fma.rn.f32x2 %0, %1, %2, %3;" : "=l"(d) : "l"(a), "l"(b), "l"(c));
    return d;
}
__device__ __forceinline__ void touch4(const float4* p){
    float a, b, c, d;
    asm volatile("ld.global.ca.v4.f32 {%0,%1,%2,%3}, [%4];"
                 : "=f"(a), "=f"(b), "=f"(c), "=f"(d) : "l"(p));
}

// ======== the ONE kernel: prep+fsetup+gemm+feval+ladder+hsum ================
#define FEVAL_I 8
__global__ void __launch_bounds__(256, 1) __cluster_dims__(2, 1, 1)
mega_kernel(const float* __restrict__ x,
            const float* __restrict__ weight,
            const float* __restrict__ bias,
            const float* __restrict__ A,
            const float* __restrict__ W1,
            const float* __restrict__ b1,
            const float* __restrict__ W2,
            const float* __restrict__ b2,
            float* __restrict__ d_out)
{
    extern __shared__ __align__(16) float dyn[];   // 66560 B
    __shared__ float red[256];
    __shared__ float key[256]; __shared__ int sidx[256];
    __shared__ float asA[256], bsA[256];
    __shared__ int   upA[256];
    __shared__ float UA[256], UB[256], DA[256], DB[256];

    int t = threadIdx.x, bid = blockIdx.x;
    unsigned gen = 0;

    // ---------- phase 0: prep (distributed) -------------------------------
    {
        float labs = 0.f;
        if (t < 128){
            int idx = bid*128 + t;
            float w = weight[idx] * A[idx];
            int r = idx >> 7, c = idx & 127;
            g_Wt[c*Dd + r] = w;
            g_M[idx] = (r == c ? 1.f : 0.f) + (w*w)*(1.f/128.f);
            labs = fabsf(w);
        }
        {
            int w = t >> 5, lane = t & 31;
            if (w < 2){
                int row = bid*2 + w;
                const float* p = W2 + row*128;
                float v = (p[lane] + p[lane+32]) + (p[lane+64] + p[lane+96]);
                #pragma unroll
                for (int s = 16; s > 0; s >>= 1)
                    v += __shfl_xor_sync(0xffffffffu, v, s);
                if (lane == 0) g_s2[row] = v;
            }
        }
        if (bid == 0){
            red[t] = (t < 128) ? b2[t] : 0.f;
            __syncthreads();
            for (int s = 128; s > 0; s >>= 1){
                if (t < s) red[t] += red[t + s];
                __syncthreads();
            }
            if (t == 0) g_B2 = red[0];
            __syncthreads();
        }
        red[t] = labs;
        __syncthreads();
        for (int s = 128; s > 0; s >>= 1){
            if (t < s) red[t] += red[t + s];
            __syncthreads();
        }
        if (t == 0) g_regP[bid] = red[0];
    }
    gen = gridbar_c(gen);                               // b1

    // ---------- phase 1a: reg final (block 0) ------------------------------
    if (bid == 0){
        red[t] = (t < 128) ? g_regP[t] : 0.f;
        __syncthreads();
        for (int s = 128; s > 0; s >>= 1){
            if (t < s) red[t] += red[t + s];
            __syncthreads();
        }
        if (t == 0) d_out[Nn*Dd + 1] = red[0];
    }
    __syncthreads();

    // ---------- phase 1b: fsetup (block b = column b) -----------------------
    {
        int i = bid;
        float a = W1[i*H1h + t];
        float bb = b1[t];
        float s = __ldcg(&g_s2[t]);
        float as = a*s, bs = bb*s;
        float tb; int up; float c0 = 0.f;
        if (a > 0.f)      { tb = -bb/a; up = 1; }
        else if (a < 0.f) { tb = -bb/a; up = 0; }
        else { tb = __int_as_float(0x7f800000); up = 1; as = 0.f; bs = 0.f;
               c0 = fmaxf(bb, 0.f) * s; }

        key[t] = tb; sidx[t] = t;
        asA[t] = as; bsA[t] = bs; upA[t] = up;
        __syncthreads();

        for (int ksz = 2; ksz <= 256; ksz <<= 1){
            for (int jsz = ksz >> 1; jsz > 0; jsz >>= 1){
                int ixj = t ^ jsz;
                float k0 = key[t], k1 = key[ixj];
                int   i0 = sidx[t], i1 = sidx[ixj];
                __syncthreads();
                if (ixj > t){
                    bool asc = ((t & ksz) == 0);
                    bool sw  = asc ? (k0 > k1) : (k0 < k1);
                    if (sw){ key[t] = k1; key[ixj] = k0;
                             sidx[t] = i1; sidx[ixj] = i0; }
                }
                __syncthreads();
            }
        }

        int o = sidx[t];
        float pas = asA[o], pbs = bsA[o];
        int pup = upA[o];
        UA[t] = pup ? pas : 0.f;  UB[t] = pup ? pbs : 0.f;
        DA[t] = pup ? 0.f : pas;  DB[t] = pup ? 0.f : pbs;
        __syncthreads();

        for (int off = 1; off < 256; off <<= 1){
            float ua = (t >= off) ? UA[t-off] : 0.f;
            float ub = (t >= off) ? UB[t-off] : 0.f;
            float da = (t >= off) ? DA[t-off] : 0.f;
            float db = (t >= off) ? DB[t-off] : 0.f;
            __syncthreads();
            UA[t] += ua; UB[t] += ub; DA[t] += da; DB[t] += db;
            __syncthreads();
        }

        red[t] = c0;
        __syncthreads();
        for (int st = 128; st > 0; st >>= 1){
            if (t < st) red[t] += red[t + st];
            __syncthreads();
        }
        float C0 = red[0] + __ldcg(&g_B2);
        float totDA = DA[255], totDB = DB[255];

        float exUA = (t > 0) ? UA[t-1] : 0.f;
        float exUB = (t > 0) ? UB[t-1] : 0.f;
        float exDA = (t > 0) ? DA[t-1] : 0.f;
        float exDB = (t > 0) ? DB[t-1] : 0.f;

        g_T [i*256 + t] = key[t];
        g_Pa[i*257 + t] = exUA + (totDA - exDA);
        g_Pb[i*257 + t] = exUB + (totDB - exDB) + C0;
        if (t == 255){
            g_Pa[i*257 + 256] = UA[255];
            g_Pb[i*257 + 256] = UB[255] + C0;
        }
    }
    __syncthreads();

    // ---------- phase 1c: gemm  y = x @ W + bias (math unchanged) ----------
    {
        float* xs = dyn;                    // 16KB
        int n0 = bid * 32;
        for (int idx = t; idx < 32*128; idx += 256)
            xs[idx] = x[n0*128 + idx];
        __syncthreads();

        int i  = t & 127;
        int ng = t >> 7;
        const ulonglong2* wrow2 = (const ulonglong2*)(g_Wt + i*128);
        u64 acc[16];
        #pragma unroll
        for (int u = 0; u < 16; u++) acc[u] = 0ULL;

        #pragma unroll 4
        for (int q = 0; q < 32; q++){
            ulonglong2 wv = wrow2[q];
            u64 w01 = wv.x, w23 = wv.y;
            #pragma unroll
            for (int u = 0; u < 16; u++){
                const u64* xp = (const u64*)&xs[(ng*16 + u)*128 + q*4];
                acc[u] = fma2(xp[0], w01, acc[u]);
                acc[u] = fma2(xp[1], w23, acc[u]);
            }
        }
        float bi = bias[i];
        #pragma unroll
        for (int u = 0; u < 16; u++){
            float p, q; upk2(acc[u], p, q);
            g_y[(n0 + ng*16 + u)*Dd + i] = (p + q) + bi;
        }
    }
    gen = gridbar_c(gen);                               // b2

    // ---------- phase 2: feval ---------------------------------------------
    {
        float* sT  = dyn;                   // [8][257]
        float* sPa = sT  + FEVAL_I*257;
        float* sPb = sPa + FEVAL_I*257;
        int i0 = (bid & 15) * FEVAL_I;

        __syncthreads();
        for (int idx = t; idx < FEVAL_I*257; idx += 256){
            int ii = idx / 257, kk = idx - ii*257;
            sT [idx] = (kk < 256) ? __ldcg(&g_T[(i0+ii)*256 + kk])
                                  : __int_as_float(0x7f800000);
            sPa[idx] = __ldcg(&g_Pa[(i0+ii)*257 + kk]);
            sPb[idx] = __ldcg(&g_Pb[(i0+ii)*257 + kk]);
        }
        __syncthreads();

        int li = t & 7, rg = t >> 3;
        const float* Tl  = sT  + li*257;
        const float* Pal = sPa + li*257;
        const float* Pbl = sPb + li*257;

        #pragma unroll
        for (int q = 0; q < 4; q++){
            int n0 = ((bid >> 4) + 8*q) * 128;
            float yv[4];
            int   kk[4];
            #pragma unroll
            for (int p = 0; p < 4; p++){
                yv[p] = __ldcg(&g_y[(n0 + rg + p*32)*Dd + i0 + li]);
                kk[p] = 0;
            }
            #pragma unroll
            for (int stp = 128; stp > 0; stp >>= 1){
                #pragma unroll
                for (int p = 0; p < 4; p++)
                    if (Tl[kk[p] + stp - 1] < yv[p]) kk[p] += stp;
            }
            #pragma unroll
            for (int p = 0; p < 4; p++)
                d_out[(n0 + rg + p*32)*Dd + i0 + li]
                    = fmaf(yv[p], Pal[kk[p]], Pbl[kk[p]]);
        }
    }
    __syncthreads();   // dyn reuse; ladder L1 reads only g_M (complete since b1)

    // ---------- phase 3: ladder — smem-staged R (row-major), LDS ring-8 ----
    {
        float* Rt = dyn;                    // 128*128 floats
        float* Ls = dyn + 128*128;          // 256 floats
        int j = t & 127, h = t >> 7;
        for (int lv = 0; lv < 7; lv++){
            int two = g_lvl2[lv];
            int p   = two ? (bid >> 6)     : 0;
            int nr  = two ? 2              : 1;
            int rb  = two ? (bid & 63) * 2 : bid;
            const float* L  = g_lvlL[lv*2 + p];
            const float* R  = g_lvlR[lv*2 + p];
            float*       Dm = g_lvlD[lv*2 + p];

            // stage R row-major into smem (conflict-free float4 copy)
            {
                const float4* R4 = (const float4*)R;
                float4* S4 = (float4*)Rt;
                #pragma unroll
                for (int q = t; q < 4096; q += 256)
                    S4[q] = __ldcg(R4 + q);
            }
            if (t < nr*128) Ls[t] = __ldcg(L + rb*128 + t);
            __syncthreads();
            if (h < nr){
                const float* Lr = Ls + h*128;
                const float* Rj = Rt + j;
                float buf[8];
                #pragma unroll
                for (int k = 0; k < 8; k++) buf[k] = Rj[k*128];
                float acc = 0.f;                 // single-acc ascending-k
                #pragma unroll
                for (int k = 0; k < 120; k++){
                    float v = buf[k & 7];
                    buf[k & 7] = Rj[(k+8)*128];
                    acc = fmaf(Lr[k], v, acc);
                }
                #pragma unroll
                for (int k = 120; k < 128; k++)
                    acc = fmaf(Lr[k], buf[k & 7], acc);
                Dm[(rb + h)*128 + j] = acc;
            }
            gen = gridbar_c(gen);                       // b3..b9
        }
    }

    // ---------- phase 3.5: transpose P127 -> ET -----------------------------
    if (t < 128)
        g_ET[bid*128 + t] = __ldcg(&g_P127[t*128 + bid]);
    gen = gridbar_c(gen);                               // b10

    // ---------- phase 4: hsum (block 0; identical FMA order) ----------------
    if (bid == 0){
        for (int q = t; q < 4096; q += 256){
            touch4((const float4*)g_ET + q);
            touch4((const float4*)g_M  + q);
        }
        __syncthreads();
        if (t < 32){
            __shared__ float pp[32];
            int l = t;
            float bufE[8], bufM[8];
            #pragma unroll
            for (int q = 0; q < 8; q++){
                int idx = l + (q << 5);
                bufE[q] = g_ET[idx];
                bufM[q] = g_M[idx];
            }
            float s = 0.f;
            for (int it = 0; it < 504; it++){
                float e = bufE[it & 7], m = bufM[it & 7];
                int idx = l + ((it + 8) << 5);
                bufE[it & 7] = g_ET[idx];
                bufM[it & 7] = g_M[idx];
                s = fmaf(e, m, s);
            }
            #pragma unroll
            for (int it = 504; it < 512; it++)
                s = fmaf(bufE[it & 7], bufM[it & 7], s);
            pp[l] = s;
            __syncwarp();
            for (int st = 16; st > 0; st >>= 1){
                if (l < st) pp[l] += pp[l + st];
                __syncwarp();
            }
            if (l == 0) d_out[Nn*Dd] = pp[0] - 128.f;
        }
    }
}

// ---------------- launch ------------------------------------------------------
extern "C" void kernel_launch(void* const* d_in, const int* in_sizes, int n_in,
                              void* d_out, int out_size)
{
    (void)in_sizes; (void)n_in; (void)out_size;
    const float* x      = (const float*)d_in[0];
    const float* weight = (const float*)d_in[1];
    const float* bias   = (const float*)d_in[2];
    const float* A      = (const float*)d_in[3];
    const float* W1     = (const float*)d_in[4];
    const float* b1     = (const float*)d_in[5];
    const float* W2     = (const float*)d_in[6];
    const float* b2     = (const float*)d_in[7];
    float* out = (float*)d_out;

    const int MEGA_SMEM = (128*128 + 256)*(int)sizeof(float);  // 66560

    static bool attr_done = false;
    if (!attr_done){
        cudaFuncSetAttribute(mega_kernel,
                             cudaFuncAttributeMaxDynamicSharedMemorySize, MEGA_SMEM);
        attr_done = true;
    }

    mega_kernel<<<128, 256, MEGA_SMEM>>>(x, weight, bias, A, W1, b1, W2, b2, out);
}

// round 13
// speedup vs baseline: 1.6700x; 1.3023x over previous
#include <cuda_runtime.h>

#define Nn 4096
#define Dd 128
#define H1h 256

typedef unsigned long long u64;

// ---------------- device scratch (all matrices 128B-aligned) ----------------
__device__ __align__(128) float g_Wt [Dd*Dd];
__device__ __align__(128) float g_M  [Dd*Dd];
__device__ __align__(128) float g_P2[Dd*Dd],  g_P3[Dd*Dd],  g_P4[Dd*Dd],  g_P7[Dd*Dd];
__device__ __align__(128) float g_P8[Dd*Dd],  g_P15[Dd*Dd], g_P16[Dd*Dd], g_P31[Dd*Dd];
__device__ __align__(128) float g_P32[Dd*Dd], g_P63[Dd*Dd], g_P64[Dd*Dd], g_P127[Dd*Dd];
__device__ __align__(128) float g_ET [Dd*Dd];
__device__ float g_s2[H1h];
__device__ float g_B2;
__device__ float g_regP[128];
__device__ __align__(128) float g_y [Nn*Dd];
__device__ float g_T [Dd*256];
__device__ float g_Pa[Dd*257];
__device__ float g_Pb[Dd*257];

// ladder level tables: [lv*2 + product]
__device__ float* const g_lvlL[14] = {g_M,g_M,  g_M,g_P2,  g_P3,g_P4,  g_P7,g_P8,
                                      g_P15,g_P16, g_P31,g_P32, g_P63,g_P63};
__device__ float* const g_lvlR[14] = {g_M,g_M,  g_P2,g_P2, g_P4,g_P4,  g_P8,g_P8,
                                      g_P16,g_P16, g_P32,g_P32, g_P64,g_P64};
__device__ float* const g_lvlD[14] = {g_P2,g_P2, g_P3,g_P4, g_P7,g_P8,  g_P15,g_P16,
                                      g_P31,g_P32, g_P63,g_P64, g_P127,g_P127};
__device__ const int g_lvl2[7] = {0,1,1,1,1,1,0};

// -------- three barrier objects: full(128), squadC(64), squadL(64) ----------
__device__ volatile unsigned g_genF = 0;
__device__ unsigned g_leafF[16*32];
__device__ unsigned g_rootF = 0;
__device__ volatile unsigned g_genC = 0;
__device__ unsigned g_leafC[8*32];
__device__ unsigned g_rootC = 0;
__device__ volatile unsigned g_genL = 0;
__device__ unsigned g_leafL[8*32];
__device__ unsigned g_rootL = 0;

// Tree barrier with absolute-target release (replay-safe: release WRITES the
// target value, waiters compare equality; counters always return to 0).
__device__ __forceinline__ void barX(volatile unsigned* genp, unsigned* leaf,
                                     unsigned* root, unsigned sid,
                                     unsigned nleaf, unsigned perleaf,
                                     unsigned target){
    __syncthreads();
    if (threadIdx.x == 0){
        __threadfence();
        unsigned lf = sid & (nleaf - 1u);
        if (atomicAdd(&leaf[lf*32], 1u) == perleaf - 1u){
            leaf[lf*32] = 0;
            __threadfence();
            if (atomicAdd(root, 1u) == nleaf - 1u){
                *root = 0;
                __threadfence();
                *genp = target;
            }
        }
        while (*genp != target){
            #pragma unroll
            for (int q = 0; q < 40; q++) asm volatile("");
        }
    }
    __syncthreads();
}

// ---------------- helpers ----------------------------------------------------
__device__ __forceinline__ void upk2(u64 v, float& lo, float& hi){
    asm("mov.b64 {%0, %1}, %2;" : "=f"(lo), "=f"(hi) : "l"(v));
}
__device__ __forceinline__ u64 fma2(u64 a, u64 b, u64 c){
    u64 d; asm("fma.rn.f32x2 %0, %1, %2, %3;" : "=l"(d) : "l"(a), "l"(b), "l"(c));
    return d;
}
__device__ __forceinline__ void touch4(const float4* p){
    float a, b, c, d;
    asm volatile("ld.global.ca.v4.f32 {%0,%1,%2,%3}, [%4];"
                 : "=f"(a), "=f"(b), "=f"(c), "=f"(d) : "l"(p));
}

// ======== ONE kernel: prep+fsetup, then {gemm+feval} || {ladder}, hsum ======
#define FEVAL_I 8
__global__ void __launch_bounds__(256, 1)
mega_kernel(const float* __restrict__ x,
            const float* __restrict__ weight,
            const float* __restrict__ bias,
            const float* __restrict__ A,
            const float* __restrict__ W1,
            const float* __restrict__ b1,
            const float* __restrict__ W2,
            const float* __restrict__ b2,
            float* __restrict__ d_out)
{
    extern __shared__ __align__(16) float dyn[];   // 67584 B
    __shared__ float red[256];
    __shared__ float key[256]; __shared__ int sidx[256];
    __shared__ float asA[256], bsA[256];
    __shared__ int   upA[256];
    __shared__ float UA[256], UB[256], DA[256], DB[256];

    int t = threadIdx.x, bid = blockIdx.x;
    bool isC = (bid < 64);
    unsigned sid = isC ? (unsigned)bid : (unsigned)(bid - 64);

    // ---------- phase 0: prep (all 128 CTAs) -------------------------------
    {
        float labs = 0.f;
        if (t < 128){
            int idx = bid*128 + t;
            float w = weight[idx] * A[idx];
            int r = idx >> 7, c = idx & 127;
            g_Wt[c*Dd + r] = w;
            g_M[idx] = (r == c ? 1.f : 0.f) + (w*w)*(1.f/128.f);
            labs = fabsf(w);
        }
        {
            int w = t >> 5, lane = t & 31;
            if (w < 2){
                int row = bid*2 + w;
                const float* p = W2 + row*128;
                float v = (p[lane] + p[lane+32]) + (p[lane+64] + p[lane+96]);
                #pragma unroll
                for (int s = 16; s > 0; s >>= 1)
                    v += __shfl_xor_sync(0xffffffffu, v, s);
                if (lane == 0) g_s2[row] = v;
            }
        }
        if (bid == 0){
            red[t] = (t < 128) ? b2[t] : 0.f;
            __syncthreads();
            for (int s = 128; s > 0; s >>= 1){
                if (t < s) red[t] += red[t + s];
                __syncthreads();
            }
            if (t == 0) g_B2 = red[0];
            __syncthreads();
        }
        red[t] = labs;
        __syncthreads();
        for (int s = 128; s > 0; s >>= 1){
            if (t < s) red[t] += red[t + s];
            __syncthreads();
        }
        if (t == 0) g_regP[bid] = red[0];
    }
    barX(&g_genF, g_leafF, &g_rootF, (unsigned)bid, 16, 8, 1);

    if (bid == 0){
        red[t] = (t < 128) ? g_regP[t] : 0.f;
        __syncthreads();
        for (int s = 128; s > 0; s >>= 1){
            if (t < s) red[t] += red[t + s];
            __syncthreads();
        }
        if (t == 0) d_out[Nn*Dd + 1] = red[0];
    }
    __syncthreads();

    // ---------- phase 1: fsetup (all 128 CTAs, column = bid) ---------------
    {
        int i = bid;
        float a = W1[i*H1h + t];
        float bb = b1[t];
        float s = __ldcg(&g_s2[t]);
        float as = a*s, bs = bb*s;
        float tb; int up; float c0 = 0.f;
        if (a > 0.f)      { tb = -bb/a; up = 1; }
        else if (a < 0.f) { tb = -bb/a; up = 0; }
        else { tb = __int_as_float(0x7f800000); up = 1; as = 0.f; bs = 0.f;
               c0 = fmaxf(bb, 0.f) * s; }

        key[t] = tb; sidx[t] = t;
        asA[t] = as; bsA[t] = bs; upA[t] = up;
        __syncthreads();

        for (int ksz = 2; ksz <= 256; ksz <<= 1){
            for (int jsz = ksz >> 1; jsz > 0; jsz >>= 1){
                int ixj = t ^ jsz;
                float k0 = key[t], k1 = key[ixj];
                int   i0 = sidx[t], i1 = sidx[ixj];
                __syncthreads();
                if (ixj > t){
                    bool asc = ((t & ksz) == 0);
                    bool sw  = asc ? (k0 > k1) : (k0 < k1);
                    if (sw){ key[t] = k1; key[ixj] = k0;
                             sidx[t] = i1; sidx[ixj] = i0; }
                }
                __syncthreads();
            }
        }

        int o = sidx[t];
        float pas = asA[o], pbs = bsA[o];
        int pup = upA[o];
        UA[t] = pup ? pas : 0.f;  UB[t] = pup ? pbs : 0.f;
        DA[t] = pup ? 0.f : pas;  DB[t] = pup ? 0.f : pbs;
        __syncthreads();

        for (int off = 1; off < 256; off <<= 1){
            float ua = (t >= off) ? UA[t-off] : 0.f;
            float ub = (t >= off) ? UB[t-off] : 0.f;
            float da = (t >= off) ? DA[t-off] : 0.f;
            float db = (t >= off) ? DB[t-off] : 0.f;
            __syncthreads();
            UA[t] += ua; UB[t] += ub; DA[t] += da; DB[t] += db;
            __syncthreads();
        }

        red[t] = c0;
        __syncthreads();
        for (int st = 128; st > 0; st >>= 1){
            if (t < st) red[t] += red[t + st];
            __syncthreads();
        }
        float C0 = red[0] + __ldcg(&g_B2);
        float totDA = DA[255], totDB = DB[255];

        float exUA = (t > 0) ? UA[t-1] : 0.f;
        float exUB = (t > 0) ? UB[t-1] : 0.f;
        float exDA = (t > 0) ? DA[t-1] : 0.f;
        float exDB = (t > 0) ? DB[t-1] : 0.f;

        g_T [i*256 + t] = key[t];
        g_Pa[i*257 + t] = exUA + (totDA - exDA);
        g_Pb[i*257 + t] = exUB + (totDB - exDB) + C0;
        if (t == 255){
            g_Pa[i*257 + 256] = UA[255];
            g_Pb[i*257 + 256] = UB[255] + C0;
        }
    }
    barX(&g_genF, g_leafF, &g_rootF, (unsigned)bid, 16, 8, 2);

    if (isC){
        // ================= compute squad: gemm (64 rows) then feval ========
        for (int pp = 0; pp < 2; pp++){
            float* xs = dyn;                    // 16KB
            int n0 = bid*64 + pp*32;
            __syncthreads();
            for (int idx = t; idx < 32*128; idx += 256)
                xs[idx] = x[n0*128 + idx];
            __syncthreads();

            int i  = t & 127;
            int ng = t >> 7;
            const ulonglong2* wrow2 = (const ulonglong2*)(g_Wt + i*128);
            u64 acc[16];
            #pragma unroll
            for (int u = 0; u < 16; u++) acc[u] = 0ULL;

            #pragma unroll 4
            for (int q = 0; q < 32; q++){
                ulonglong2 wv = wrow2[q];
                u64 w01 = wv.x, w23 = wv.y;
                #pragma unroll
                for (int u = 0; u < 16; u++){
                    const u64* xp = (const u64*)&xs[(ng*16 + u)*128 + q*4];
                    acc[u] = fma2(xp[0], w01, acc[u]);
                    acc[u] = fma2(xp[1], w23, acc[u]);
                }
            }
            float bi = bias[i];
            #pragma unroll
            for (int u = 0; u < 16; u++){
                float p, q; upk2(acc[u], p, q);
                g_y[(n0 + ng*16 + u)*Dd + i] = (p + q) + bi;
            }
        }
        barX(&g_genC, g_leafC, &g_rootC, sid, 8, 8, 1);   // y complete

        // feval: tables once, 8 n-tiles of 128 rows
        {
            float* sT  = dyn;
            float* sPa = sT  + FEVAL_I*257;
            float* sPb = sPa + FEVAL_I*257;
            int i0 = (bid & 15) * FEVAL_I;

            for (int idx = t; idx < FEVAL_I*257; idx += 256){
                int ii = idx / 257, kk = idx - ii*257;
                sT [idx] = (kk < 256) ? __ldcg(&g_T[(i0+ii)*256 + kk])
                                      : __int_as_float(0x7f800000);
                sPa[idx] = __ldcg(&g_Pa[(i0+ii)*257 + kk]);
                sPb[idx] = __ldcg(&g_Pb[(i0+ii)*257 + kk]);
            }
            __syncthreads();

            int li = t & 7, rg = t >> 3;
            const float* Tl  = sT  + li*257;
            const float* Pal = sPa + li*257;
            const float* Pbl = sPb + li*257;

            #pragma unroll
            for (int q = 0; q < 8; q++){
                int n0 = (bid >> 4)*1024 + q*128;
                float yv[4];
                int   kk[4];
                #pragma unroll
                for (int p = 0; p < 4; p++){
                    yv[p] = __ldcg(&g_y[(n0 + rg + p*32)*Dd + i0 + li]);
                    kk[p] = 0;
                }
                #pragma unroll
                for (int stp = 128; stp > 0; stp >>= 1){
                    #pragma unroll
                    for (int p = 0; p < 4; p++)
                        if (Tl[kk[p] + stp - 1] < yv[p]) kk[p] += stp;
                }
                #pragma unroll
                for (int p = 0; p < 4; p++)
                    d_out[(n0 + rg + p*32)*Dd + i0 + li]
                        = fmaf(yv[p], Pal[kk[p]], Pbl[kk[p]]);
            }
        }
    } else {
        // ================= ladder squad: 7 levels, 64 CTAs =================
        float* Rt = dyn;                    // 128*128 floats
        float* Ls = dyn + 128*128;          // up to 512 floats
        int j = t & 127, h = t >> 7;
        for (int lv = 0; lv < 7; lv++){
            int two = g_lvl2[lv];
            const float* L; const float* R; float* Dm;
            int rbase;
            if (two){
                int p = (int)(sid >> 5);          // 32 CTAs per product
                rbase = (int)(sid & 31) * 4;      // 4 rows
                L = g_lvlL[lv*2 + p]; R = g_lvlR[lv*2 + p]; Dm = g_lvlD[lv*2 + p];
            } else {
                rbase = (int)sid * 2;             // 2 rows
                L = g_lvlL[lv*2]; R = g_lvlR[lv*2]; Dm = g_lvlD[lv*2];
            }

            // stage R row-major into smem (conflict-free float4 copy)
            {
                const float4* R4 = (const float4*)R;
                float4* S4 = (float4*)Rt;
                #pragma unroll
                for (int q = t; q < 4096; q += 256)
                    S4[q] = __ldcg(R4 + q);
            }
            if (two){
                Ls[t]       = __ldcg(L + rbase*128 + t);
                Ls[t + 256] = __ldcg(L + rbase*128 + t + 256);
            } else {
                Ls[t] = __ldcg(L + rbase*128 + t);
            }
            __syncthreads();

            const float* Rj = Rt + j;
            float buf[8];
            #pragma unroll
            for (int k = 0; k < 8; k++) buf[k] = Rj[k*128];

            if (two){
                const float* L0 = Ls + h*128;
                const float* L1 = L0 + 256;       // row +2
                float a0 = 0.f, a1 = 0.f;         // two single-acc chains
                #pragma unroll
                for (int k = 0; k < 120; k++){
                    float v = buf[k & 7];
                    buf[k & 7] = Rj[(k+8)*128];
                    a0 = fmaf(L0[k], v, a0);
                    a1 = fmaf(L1[k], v, a1);
                }
                #pragma unroll
                for (int k = 120; k < 128; k++){
                    float v = buf[k & 7];
                    a0 = fmaf(L0[k], v, a0);
                    a1 = fmaf(L1[k], v, a1);
                }
                Dm[(rbase + h)*128 + j]     = a0;
                Dm[(rbase + h + 2)*128 + j] = a1;
            } else {
                const float* L0 = Ls + h*128;
                float a0 = 0.f;                   // single-acc ascending-k
                #pragma unroll
                for (int k = 0; k < 120; k++){
                    float v = buf[k & 7];
                    buf[k & 7] = Rj[(k+8)*128];
                    a0 = fmaf(L0[k], v, a0);
                }
                #pragma unroll
                for (int k = 120; k < 128; k++)
                    a0 = fmaf(L0[k], buf[k & 7], a0);
                Dm[(rbase + h)*128 + j] = a0;
            }
            __syncthreads();
            barX(&g_genL, g_leafL, &g_rootL, sid, 8, 8, (unsigned)(lv + 1));
        }

        // transpose P127 -> ET (2 columns per CTA)
        {
            int c  = (int)sid*2 + h;
            g_ET[c*128 + j] = __ldcg(&g_P127[j*128 + c]);
        }
    }
    barX(&g_genF, g_leafF, &g_rootF, (unsigned)bid, 16, 8, 3);

    // ---------- hsum (block 0; identical FMA order) -------------------------
    if (bid == 0){
        for (int q = t; q < 4096; q += 256){
            touch4((const float4*)g_ET + q);
            touch4((const float4*)g_M  + q);
        }
        __syncthreads();
        if (t < 32){
            __shared__ float pp[32];
            int l = t;
            float bufE[8], bufM[8];
            #pragma unroll
            for (int q = 0; q < 8; q++){
                int idx = l + (q << 5);
                bufE[q] = g_ET[idx];
                bufM[q] = g_M[idx];
            }
            float s = 0.f;
            for (int it = 0; it < 504; it++){
                float e = bufE[it & 7], m = bufM[it & 7];
                int idx = l + ((it + 8) << 5);
                bufE[it & 7] = g_ET[idx];
                bufM[it & 7] = g_M[idx];
                s = fmaf(e, m, s);
            }
            #pragma unroll
            for (int it = 504; it < 512; it++)
                s = fmaf(bufE[it & 7], bufM[it & 7], s);
            pp[l] = s;
            __syncwarp();
            for (int st = 16; st > 0; st >>= 1){
                if (l < st) pp[l] += pp[l + st];
                __syncwarp();
            }
            if (l == 0) d_out[Nn*Dd] = pp[0] - 128.f;
        }
    }
}

// ---------------- launch ------------------------------------------------------
extern "C" void kernel_launch(void* const* d_in, const int* in_sizes, int n_in,
                              void* d_out, int out_size)
{
    (void)in_sizes; (void)n_in; (void)out_size;
    const float* x      = (const float*)d_in[0];
    const float* weight = (const float*)d_in[1];
    const float* bias   = (const float*)d_in[2];
    const float* A      = (const float*)d_in[3];
    const float* W1     = (const float*)d_in[4];
    const float* b1     = (const float*)d_in[5];
    const float* W2     = (const float*)d_in[6];
    const float* b2     = (const float*)d_in[7];
    float* out = (float*)d_out;

    const int MEGA_SMEM = (128*128 + 512)*(int)sizeof(float);  // 67584

    static bool attr_done = false;
    if (!attr_done){
        cudaFuncSetAttribute(mega_kernel,
                             cudaFuncAttributeMaxDynamicSharedMemorySize, MEGA_SMEM);
        attr_done = true;
    }

    mega_kernel<<<128, 256, MEGA_SMEM>>>(x, weight, bias, A, W1, b1, W2, b2, out);
}

// round 14
// speedup vs baseline: 1.7356x; 1.0393x over previous
#include <cuda_runtime.h>

#define Nn 4096
#define Dd 128
#define H1h 256

typedef unsigned long long u64;

// ---------------- device scratch (all matrices 128B-aligned) ----------------
__device__ __align__(128) float g_Wt [Dd*Dd];
__device__ __align__(128) float g_M  [Dd*Dd];
__device__ __align__(128) float g_P2[Dd*Dd],  g_P3[Dd*Dd],  g_P4[Dd*Dd],  g_P7[Dd*Dd];
__device__ __align__(128) float g_P8[Dd*Dd],  g_P15[Dd*Dd], g_P16[Dd*Dd], g_P31[Dd*Dd];
__device__ __align__(128) float g_P32[Dd*Dd], g_P63[Dd*Dd], g_P64[Dd*Dd], g_P127[Dd*Dd];
__device__ __align__(128) float g_ET [Dd*Dd];
__device__ float g_s2[H1h];
__device__ float g_B2;
__device__ float g_regP[128];
__device__ __align__(128) float g_y [Nn*Dd];
__device__ float g_T [Dd*256];
__device__ float g_Pa[Dd*257];
__device__ float g_Pb[Dd*257];

// ladder level tables: [lv*2 + product]
__device__ float* const g_lvlL[14] = {g_M,g_M,  g_M,g_P2,  g_P3,g_P4,  g_P7,g_P8,
                                      g_P15,g_P16, g_P31,g_P32, g_P63,g_P63};
__device__ float* const g_lvlR[14] = {g_M,g_M,  g_P2,g_P2, g_P4,g_P4,  g_P8,g_P8,
                                      g_P16,g_P16, g_P32,g_P32, g_P64,g_P64};
__device__ float* const g_lvlD[14] = {g_P2,g_P2, g_P3,g_P4, g_P7,g_P8,  g_P15,g_P16,
                                      g_P31,g_P32, g_P63,g_P64, g_P127,g_P127};
__device__ const int g_lvl2[7] = {0,1,1,1,1,1,0};

// -------- three barrier objects: full(128), squadC(64), squadL(64) ----------
__device__ volatile unsigned g_genF = 0;
__device__ unsigned g_leafF[16*32];
__device__ unsigned g_rootF = 0;
__device__ volatile unsigned g_genC = 0;
__device__ unsigned g_leafC[8*32];
__device__ unsigned g_rootC = 0;
__device__ volatile unsigned g_genL = 0;
__device__ unsigned g_leafL[8*32];
__device__ unsigned g_rootL = 0;

// Tree barrier with absolute-target release (replay-safe: release WRITES the
// target value, waiters compare equality; counters always return to 0).
__device__ __forceinline__ void barX(volatile unsigned* genp, unsigned* leaf,
                                     unsigned* root, unsigned sid,
                                     unsigned nleaf, unsigned perleaf,
                                     unsigned target){
    __syncthreads();
    if (threadIdx.x == 0){
        __threadfence();
        unsigned lf = sid & (nleaf - 1u);
        if (atomicAdd(&leaf[lf*32], 1u) == perleaf - 1u){
            leaf[lf*32] = 0;
            __threadfence();
            if (atomicAdd(root, 1u) == nleaf - 1u){
                *root = 0;
                __threadfence();
                *genp = target;
            }
        }
        while (*genp != target){
            #pragma unroll
            for (int q = 0; q < 40; q++) asm volatile("");
        }
    }
    __syncthreads();
}

// ---------------- helpers ----------------------------------------------------
__device__ __forceinline__ void upk2(u64 v, float& lo, float& hi){
    asm("mov.b64 {%0, %1}, %2;" : "=f"(lo), "=f"(hi) : "l"(v));
}
__device__ __forceinline__ u64 fma2(u64 a, u64 b, u64 c){
    u64 d; asm("fma.rn.f32x2 %0, %1, %2, %3;" : "=l"(d) : "l"(a), "l"(b), "l"(c));
    return d;
}
__device__ __forceinline__ void touch4(const float4* p){
    float a, b, c, d;
    asm volatile("ld.global.ca.v4.f32 {%0,%1,%2,%3}, [%4];"
                 : "=f"(a), "=f"(b), "=f"(c), "=f"(d) : "l"(p));
}

// ======== ONE kernel: prep+fsetup, then {gemm+feval} || {ladder}, hsum ======
#define FEVAL_I 8
__global__ void __launch_bounds__(256, 1)
mega_kernel(const float* __restrict__ x,
            const float* __restrict__ weight,
            const float* __restrict__ bias,
            const float* __restrict__ A,
            const float* __restrict__ W1,
            const float* __restrict__ b1,
            const float* __restrict__ W2,
            const float* __restrict__ b2,
            float* __restrict__ d_out)
{
    extern __shared__ __align__(16) float dyn[];   // 67584 B
    __shared__ float red[256];
    __shared__ float key[256]; __shared__ int sidx[256];
    __shared__ float asA[256], bsA[256];
    __shared__ int   upA[256];
    __shared__ float UA[256], UB[256], DA[256], DB[256];

    int t = threadIdx.x, bid = blockIdx.x;
    bool isC = (bid < 64);
    unsigned sid = isC ? (unsigned)bid : (unsigned)(bid - 64);

    // ---------- phase 0: prep (all 128 CTAs) -------------------------------
    {
        float labs = 0.f;
        if (t < 128){
            int idx = bid*128 + t;
            float w = weight[idx] * A[idx];
            int r = idx >> 7, c = idx & 127;
            g_Wt[c*Dd + r] = w;
            g_M[idx] = (r == c ? 1.f : 0.f) + (w*w)*(1.f/128.f);
            labs = fabsf(w);
        }
        {
            int w = t >> 5, lane = t & 31;
            if (w < 2){
                int row = bid*2 + w;
                const float* p = W2 + row*128;
                float v = (p[lane] + p[lane+32]) + (p[lane+64] + p[lane+96]);
                #pragma unroll
                for (int s = 16; s > 0; s >>= 1)
                    v += __shfl_xor_sync(0xffffffffu, v, s);
                if (lane == 0) g_s2[row] = v;
            }
        }
        if (bid == 0){
            red[t] = (t < 128) ? b2[t] : 0.f;
            __syncthreads();
            for (int s = 128; s > 0; s >>= 1){
                if (t < s) red[t] += red[t + s];
                __syncthreads();
            }
            if (t == 0) g_B2 = red[0];
            __syncthreads();
        }
        red[t] = labs;
        __syncthreads();
        for (int s = 128; s > 0; s >>= 1){
            if (t < s) red[t] += red[t + s];
            __syncthreads();
        }
        if (t == 0) g_regP[bid] = red[0];
    }
    barX(&g_genF, g_leafF, &g_rootF, (unsigned)bid, 16, 8, 1);

    if (bid == 0){
        red[t] = (t < 128) ? g_regP[t] : 0.f;
        __syncthreads();
        for (int s = 128; s > 0; s >>= 1){
            if (t < s) red[t] += red[t + s];
            __syncthreads();
        }
        if (t == 0) d_out[Nn*Dd + 1] = red[0];
    }
    __syncthreads();

    // ---------- phase 1: fsetup (all 128 CTAs, column = bid) ---------------
    {
        int i = bid;
        float a = W1[i*H1h + t];
        float bb = b1[t];
        float s = __ldcg(&g_s2[t]);
        float as = a*s, bs = bb*s;
        float tb; int up; float c0 = 0.f;
        if (a > 0.f)      { tb = -bb/a; up = 1; }
        else if (a < 0.f) { tb = -bb/a; up = 0; }
        else { tb = __int_as_float(0x7f800000); up = 1; as = 0.f; bs = 0.f;
               c0 = fmaxf(bb, 0.f) * s; }

        key[t] = tb; sidx[t] = t;
        asA[t] = as; bsA[t] = bs; upA[t] = up;
        __syncthreads();

        for (int ksz = 2; ksz <= 256; ksz <<= 1){
            for (int jsz = ksz >> 1; jsz > 0; jsz >>= 1){
                int ixj = t ^ jsz;
                float k0 = key[t], k1 = key[ixj];
                int   i0 = sidx[t], i1 = sidx[ixj];
                __syncthreads();
                if (ixj > t){
                    bool asc = ((t & ksz) == 0);
                    bool sw  = asc ? (k0 > k1) : (k0 < k1);
                    if (sw){ key[t] = k1; key[ixj] = k0;
                             sidx[t] = i1; sidx[ixj] = i0; }
                }
                __syncthreads();
            }
        }

        int o = sidx[t];
        float pas = asA[o], pbs = bsA[o];
        int pup = upA[o];
        UA[t] = pup ? pas : 0.f;  UB[t] = pup ? pbs : 0.f;
        DA[t] = pup ? 0.f : pas;  DB[t] = pup ? 0.f : pbs;
        __syncthreads();

        for (int off = 1; off < 256; off <<= 1){
            float ua = (t >= off) ? UA[t-off] : 0.f;
            float ub = (t >= off) ? UB[t-off] : 0.f;
            float da = (t >= off) ? DA[t-off] : 0.f;
            float db = (t >= off) ? DB[t-off] : 0.f;
            __syncthreads();
            UA[t] += ua; UB[t] += ub; DA[t] += da; DB[t] += db;
            __syncthreads();
        }

        red[t] = c0;
        __syncthreads();
        for (int st = 128; st > 0; st >>= 1){
            if (t < st) red[t] += red[t + st];
            __syncthreads();
        }
        float C0 = red[0] + __ldcg(&g_B2);
        float totDA = DA[255], totDB = DB[255];

        float exUA = (t > 0) ? UA[t-1] : 0.f;
        float exUB = (t > 0) ? UB[t-1] : 0.f;
        float exDA = (t > 0) ? DA[t-1] : 0.f;
        float exDB = (t > 0) ? DB[t-1] : 0.f;

        g_T [i*256 + t] = key[t];
        g_Pa[i*257 + t] = exUA + (totDA - exDA);
        g_Pb[i*257 + t] = exUB + (totDB - exDB) + C0;
        if (t == 255){
            g_Pa[i*257 + 256] = UA[255];
            g_Pb[i*257 + 256] = UB[255] + C0;
        }
    }
    barX(&g_genF, g_leafF, &g_rootF, (unsigned)bid, 16, 8, 2);

    if (isC){
        // ================= compute squad: gemm (64 rows) then feval ========
        for (int pp = 0; pp < 2; pp++){
            float* xs = dyn;                    // 16KB
            int n0 = bid*64 + pp*32;
            __syncthreads();
            for (int idx = t; idx < 32*128; idx += 256)
                xs[idx] = x[n0*128 + idx];
            __syncthreads();

            int i  = t & 127;
            int ng = t >> 7;
            const ulonglong2* wrow2 = (const ulonglong2*)(g_Wt + i*128);
            u64 acc[16];
            #pragma unroll
            for (int u = 0; u < 16; u++) acc[u] = 0ULL;

            #pragma unroll 4
            for (int q = 0; q < 32; q++){
                ulonglong2 wv = wrow2[q];
                u64 w01 = wv.x, w23 = wv.y;
                #pragma unroll
                for (int u = 0; u < 16; u++){
                    const u64* xp = (const u64*)&xs[(ng*16 + u)*128 + q*4];
                    acc[u] = fma2(xp[0], w01, acc[u]);
                    acc[u] = fma2(xp[1], w23, acc[u]);
                }
            }
            float bi = bias[i];
            #pragma unroll
            for (int u = 0; u < 16; u++){
                float p, q; upk2(acc[u], p, q);
                g_y[(n0 + ng*16 + u)*Dd + i] = (p + q) + bi;
            }
        }
        barX(&g_genC, g_leafC, &g_rootC, sid, 8, 8, 1);   // y complete

        // feval: tables once, 8 n-tiles of 128 rows
        {
            float* sT  = dyn;
            float* sPa = sT  + FEVAL_I*257;
            float* sPb = sPa + FEVAL_I*257;
            int i0 = (bid & 15) * FEVAL_I;

            for (int idx = t; idx < FEVAL_I*257; idx += 256){
                int ii = idx / 257, kk = idx - ii*257;
                sT [idx] = (kk < 256) ? __ldcg(&g_T[(i0+ii)*256 + kk])
                                      : __int_as_float(0x7f800000);
                sPa[idx] = __ldcg(&g_Pa[(i0+ii)*257 + kk]);
                sPb[idx] = __ldcg(&g_Pb[(i0+ii)*257 + kk]);
            }
            __syncthreads();

            int li = t & 7, rg = t >> 3;
            const float* Tl  = sT  + li*257;
            const float* Pal = sPa + li*257;
            const float* Pbl = sPb + li*257;

            #pragma unroll
            for (int q = 0; q < 8; q++){
                int n0 = (bid >> 4)*1024 + q*128;
                float yv[4];
                int   kk[4];
                #pragma unroll
                for (int p = 0; p < 4; p++){
                    yv[p] = __ldcg(&g_y[(n0 + rg + p*32)*Dd + i0 + li]);
                    kk[p] = 0;
                }
                #pragma unroll
                for (int stp = 128; stp > 0; stp >>= 1){
                    #pragma unroll
                    for (int p = 0; p < 4; p++)
                        if (Tl[kk[p] + stp - 1] < yv[p]) kk[p] += stp;
                }
                #pragma unroll
                for (int p = 0; p < 4; p++)
                    d_out[(n0 + rg + p*32)*Dd + i0 + li]
                        = fmaf(yv[p], Pal[kk[p]], Pbl[kk[p]]);
            }
        }
    } else {
        // ================= ladder squad: 7 levels, 64 CTAs =================
        float* Rt = dyn;                    // 128*128 floats
        float* Ls = dyn + 128*128;          // up to 512 floats
        int j = t & 127, h = t >> 7;
        for (int lv = 0; lv < 7; lv++){
            int two = g_lvl2[lv];
            const float* L; const float* R; float* Dm;
            int rbase;
            if (two){
                int p = (int)(sid >> 5);          // 32 CTAs per product
                rbase = (int)(sid & 31) * 4;      // 4 rows
                L = g_lvlL[lv*2 + p]; R = g_lvlR[lv*2 + p]; Dm = g_lvlD[lv*2 + p];
            } else {
                rbase = (int)sid * 2;             // 2 rows
                L = g_lvlL[lv*2]; R = g_lvlR[lv*2]; Dm = g_lvlD[lv*2];
            }

            // stage R row-major into smem (conflict-free float4 copy)
            {
                const float4* R4 = (const float4*)R;
                float4* S4 = (float4*)Rt;
                #pragma unroll
                for (int q = t; q < 4096; q += 256)
                    S4[q] = __ldcg(R4 + q);
            }
            if (two){
                Ls[t]       = __ldcg(L + rbase*128 + t);
                Ls[t + 256] = __ldcg(L + rbase*128 + t + 256);
            } else {
                Ls[t] = __ldcg(L + rbase*128 + t);
            }
            __syncthreads();

            const float* Rj = Rt + j;
            float buf[8];
            #pragma unroll
            for (int k = 0; k < 8; k++) buf[k] = Rj[k*128];

            if (two){
                const float* L0 = Ls + h*128;
                const float* L1 = L0 + 256;       // row +2
                float a0 = 0.f, a1 = 0.f;         // two single-acc chains
                #pragma unroll
                for (int k = 0; k < 120; k++){
                    float v = buf[k & 7];
                    buf[k & 7] = Rj[(k+8)*128];
                    a0 = fmaf(L0[k], v, a0);
                    a1 = fmaf(L1[k], v, a1);
                }
                #pragma unroll
                for (int k = 120; k < 128; k++){
                    float v = buf[k & 7];
                    a0 = fmaf(L0[k], v, a0);
                    a1 = fmaf(L1[k], v, a1);
                }
                Dm[(rbase + h)*128 + j]     = a0;
                Dm[(rbase + h + 2)*128 + j] = a1;
            } else {
                const float* L0 = Ls + h*128;
                float a0 = 0.f;                   // single-acc ascending-k
                #pragma unroll
                for (int k = 0; k < 120; k++){
                    float v = buf[k & 7];
                    buf[k & 7] = Rj[(k+8)*128];
                    a0 = fmaf(L0[k], v, a0);
                }
                #pragma unroll
                for (int k = 120; k < 128; k++)
                    a0 = fmaf(L0[k], buf[k & 7], a0);
                Dm[(rbase + h)*128 + j] = a0;
            }
            __syncthreads();
            barX(&g_genL, g_leafL, &g_rootL, sid, 8, 8, (unsigned)(lv + 1));
        }

        // transpose P127 -> ET (2 columns per CTA)
        {
            int c  = (int)sid*2 + h;
            g_ET[c*128 + j] = __ldcg(&g_P127[j*128 + c]);
        }
    }
    barX(&g_genF, g_leafF, &g_rootF, (unsigned)bid, 16, 8, 3);

    // ---------- hsum (block 0; identical FMA order) -------------------------
    if (bid == 0){
        for (int q = t; q < 4096; q += 256){
            touch4((const float4*)g_ET + q);
            touch4((const float4*)g_M  + q);
        }
        __syncthreads();
        if (t < 32){
            __shared__ float pp[32];
            int l = t;
            float bufE[8], bufM[8];
            #pragma unroll
            for (int q = 0; q < 8; q++){
                int idx = l + (q << 5);
                bufE[q] = g_ET[idx];
                bufM[q] = g_M[idx];
            }
            float s = 0.f;
            for (int it = 0; it < 504; it++){
                float e = bufE[it & 7], m = bufM[it & 7];
                int idx = l + ((it + 8) << 5);
                bufE[it & 7] = g_ET[idx];
                bufM[it & 7] = g_M[idx];
                s = fmaf(e, m, s);
            }
            #pragma unroll
            for (int it = 504; it < 512; it++)
                s = fmaf(bufE[it & 7], bufM[it & 7], s);
            pp[l] = s;
            __syncwarp();
            for (int st = 16; st > 0; st >>= 1){
                if (l < st) pp[l] += pp[l + st];
                __syncwarp();
            }
            if (l == 0) d_out[Nn*Dd] = pp[0] - 128.f;
        }
    }
}

// ---------------- launch ------------------------------------------------------
extern "C" void kernel_launch(void* const* d_in, const int* in_sizes, int n_in,
                              void* d_out, int out_size)
{
    (void)in_sizes; (void)n_in; (void)out_size;
    const float* x      = (const float*)d_in[0];
    const float* weight = (const float*)d_in[1];
    const float* bias   = (const float*)d_in[2];
    const float* A      = (const float*)d_in[3];
    const float* W1     = (const float*)d_in[4];
    const float* b1     = (const float*)d_in[5];
    const float* W2     = (const float*)d_in[6];
    const float* b2     = (const float*)d_in[7];
    float* out = (float*)d_out;

    const int MEGA_SMEM = (128*128 + 512)*(int)sizeof(float);  // 67584

    static bool attr_done = false;
    if (!attr_done){
        cudaFuncSetAttribute(mega_kernel,
                             cudaFuncAttributeMaxDynamicSharedMemorySize, MEGA_SMEM);
        attr_done = true;
    }

    mega_kernel<<<128, 256, MEGA_SMEM>>>(x, weight, bias, A, W1, b1, W2, b2, out);
}

// round 15
// speedup vs baseline: 1.8690x; 1.0768x over previous
#include <cuda_runtime.h>

#define Nn 4096
#define Dd 128
#define H1h 256

typedef unsigned long long u64;

// ---------------- device scratch (all matrices 128B-aligned) ----------------
__device__ __align__(128) float g_Wt [Dd*Dd];
__device__ __align__(128) float g_M  [Dd*Dd];
__device__ __align__(128) float g_P2[Dd*Dd],  g_P3[Dd*Dd],  g_P4[Dd*Dd],  g_P7[Dd*Dd];
__device__ __align__(128) float g_P8[Dd*Dd],  g_P15[Dd*Dd], g_P16[Dd*Dd], g_P31[Dd*Dd];
__device__ __align__(128) float g_P32[Dd*Dd], g_P63[Dd*Dd], g_P64[Dd*Dd], g_P127[Dd*Dd];
__device__ __align__(128) float g_ET [Dd*Dd];
__device__ float g_s2[H1h];
__device__ float g_B2;
__device__ float g_regP[128];
__device__ __align__(128) float g_y [Nn*Dd];
__device__ float g_T [Dd*256];
__device__ float g_Pa[Dd*257];
__device__ float g_Pb[Dd*257];

// ladder level tables: [lv*2 + product]
__device__ float* const g_lvlL[14] = {g_M,g_M,  g_M,g_P2,  g_P3,g_P4,  g_P7,g_P8,
                                      g_P15,g_P16, g_P31,g_P32, g_P63,g_P63};
__device__ float* const g_lvlR[14] = {g_M,g_M,  g_P2,g_P2, g_P4,g_P4,  g_P8,g_P8,
                                      g_P16,g_P16, g_P32,g_P32, g_P64,g_P64};
__device__ float* const g_lvlD[14] = {g_P2,g_P2, g_P3,g_P4, g_P7,g_P8,  g_P15,g_P16,
                                      g_P31,g_P32, g_P63,g_P64, g_P127,g_P127};
__device__ const int g_lvl2[7] = {0,1,1,1,1,1,0};

// -------- three barrier objects: full(128), squadC(64), squadL(64) ----------
__device__ volatile unsigned g_genF = 0;
__device__ unsigned g_leafF[16*32];
__device__ unsigned g_rootF = 0;
__device__ volatile unsigned g_genC = 0;
__device__ unsigned g_leafC[8*32];
__device__ unsigned g_rootC = 0;
__device__ volatile unsigned g_genL = 0;
__device__ unsigned g_leafL[8*32];
__device__ unsigned g_rootL = 0;

// Tree barrier with absolute-target release (replay-safe).
__device__ __forceinline__ void barX(volatile unsigned* genp, unsigned* leaf,
                                     unsigned* root, unsigned sid,
                                     unsigned nleaf, unsigned perleaf,
                                     unsigned target){
    __syncthreads();
    if (threadIdx.x == 0){
        __threadfence();
        unsigned lf = sid & (nleaf - 1u);
        if (atomicAdd(&leaf[lf*32], 1u) == perleaf - 1u){
            leaf[lf*32] = 0;
            __threadfence();
            if (atomicAdd(root, 1u) == nleaf - 1u){
                *root = 0;
                __threadfence();
                *genp = target;
            }
        }
        while (*genp != target){
            #pragma unroll
            for (int q = 0; q < 40; q++) asm volatile("");
        }
    }
    __syncthreads();
}

// ---------------- helpers ----------------------------------------------------
__device__ __forceinline__ void upk2(u64 v, float& lo, float& hi){
    asm("mov.b64 {%0, %1}, %2;" : "=f"(lo), "=f"(hi) : "l"(v));
}
__device__ __forceinline__ u64 fma2(u64 a, u64 b, u64 c){
    u64 d; asm("fma.rn.f32x2 %0, %1, %2, %3;" : "=l"(d) : "l"(a), "l"(b), "l"(c));
    return d;
}
__device__ __forceinline__ void touch4(const float4* p){
    float a, b, c, d;
    asm volatile("ld.global.ca.v4.f32 {%0,%1,%2,%3}, [%4];"
                 : "=f"(a), "=f"(b), "=f"(c), "=f"(d) : "l"(p));
}

// ======== ONE kernel: prep, then {fsetup+gemm+feval} || {ladder}, hsum ======
#define FEVAL_I 8
__global__ void __launch_bounds__(256, 1)
mega_kernel(const float* __restrict__ x,
            const float* __restrict__ weight,
            const float* __restrict__ bias,
            const float* __restrict__ A,
            const float* __restrict__ W1,
            const float* __restrict__ b1,
            const float* __restrict__ W2,
            const float* __restrict__ b2,
            float* __restrict__ d_out)
{
    extern __shared__ __align__(16) float dyn[];   // 67584 B
    __shared__ float red[256];
    __shared__ float key[256]; __shared__ int sidx[256];
    __shared__ float asA[256], bsA[256];
    __shared__ int   upA[256];
    __shared__ float UA[256], UB[256], DA[256], DB[256];

    int t = threadIdx.x, bid = blockIdx.x;
    bool isC = (bid < 64);
    unsigned sid = isC ? (unsigned)bid : (unsigned)(bid - 64);

    // ---------- phase 0: prep (all 128 CTAs) -------------------------------
    {
        float labs = 0.f;
        if (t < 128){
            int idx = bid*128 + t;
            float w = weight[idx] * A[idx];
            int r = idx >> 7, c = idx & 127;
            g_Wt[c*Dd + r] = w;
            g_M[idx] = (r == c ? 1.f : 0.f) + (w*w)*(1.f/128.f);
            labs = fabsf(w);
        }
        {
            int w = t >> 5, lane = t & 31;
            if (w < 2){
                int row = bid*2 + w;
                const float* p = W2 + row*128;
                float v = (p[lane] + p[lane+32]) + (p[lane+64] + p[lane+96]);
                #pragma unroll
                for (int s = 16; s > 0; s >>= 1)
                    v += __shfl_xor_sync(0xffffffffu, v, s);
                if (lane == 0) g_s2[row] = v;
            }
        }
        if (bid == 0){
            red[t] = (t < 128) ? b2[t] : 0.f;
            __syncthreads();
            for (int s = 128; s > 0; s >>= 1){
                if (t < s) red[t] += red[t + s];
                __syncthreads();
            }
            if (t == 0) g_B2 = red[0];
            __syncthreads();
        }
        red[t] = labs;
        __syncthreads();
        for (int s = 128; s > 0; s >>= 1){
            if (t < s) red[t] += red[t + s];
            __syncthreads();
        }
        if (t == 0) g_regP[bid] = red[0];
    }
    barX(&g_genF, g_leafF, &g_rootF, (unsigned)bid, 16, 8, 1);

    if (isC){
        // ============ compute squad: reg-final, fsetup x2, gemm, feval ======
        if (bid == 0){
            red[t] = (t < 128) ? g_regP[t] : 0.f;
            __syncthreads();
            for (int s = 128; s > 0; s >>= 1){
                if (t < s) red[t] += red[t + s];
                __syncthreads();
            }
            if (t == 0) d_out[Nn*Dd + 1] = red[0];
        }
        __syncthreads();

        // ---- fsetup: columns 2*sid and 2*sid+1 (same per-column math) ----
        for (int ii = 0; ii < 2; ii++){
            int i = (int)sid*2 + ii;
            float a = W1[i*H1h + t];
            float bb = b1[t];
            float s = __ldcg(&g_s2[t]);
            float as = a*s, bs = bb*s;
            float tb; int up; float c0 = 0.f;
            if (a > 0.f)      { tb = -bb/a; up = 1; }
            else if (a < 0.f) { tb = -bb/a; up = 0; }
            else { tb = __int_as_float(0x7f800000); up = 1; as = 0.f; bs = 0.f;
                   c0 = fmaxf(bb, 0.f) * s; }

            key[t] = tb; sidx[t] = t;
            asA[t] = as; bsA[t] = bs; upA[t] = up;
            __syncthreads();

            for (int ksz = 2; ksz <= 256; ksz <<= 1){
                for (int jsz = ksz >> 1; jsz > 0; jsz >>= 1){
                    int ixj = t ^ jsz;
                    float k0 = key[t], k1 = key[ixj];
                    int   i0 = sidx[t], i1 = sidx[ixj];
                    __syncthreads();
                    if (ixj > t){
                        bool asc = ((t & ksz) == 0);
                        bool sw  = asc ? (k0 > k1) : (k0 < k1);
                        if (sw){ key[t] = k1; key[ixj] = k0;
                                 sidx[t] = i1; sidx[ixj] = i0; }
                    }
                    __syncthreads();
                }
            }

            int o = sidx[t];
            float pas = asA[o], pbs = bsA[o];
            int pup = upA[o];
            UA[t] = pup ? pas : 0.f;  UB[t] = pup ? pbs : 0.f;
            DA[t] = pup ? 0.f : pas;  DB[t] = pup ? 0.f : pbs;
            __syncthreads();

            for (int off = 1; off < 256; off <<= 1){
                float ua = (t >= off) ? UA[t-off] : 0.f;
                float ub = (t >= off) ? UB[t-off] : 0.f;
                float da = (t >= off) ? DA[t-off] : 0.f;
                float db = (t >= off) ? DB[t-off] : 0.f;
                __syncthreads();
                UA[t] += ua; UB[t] += ub; DA[t] += da; DB[t] += db;
                __syncthreads();
            }

            red[t] = c0;
            __syncthreads();
            for (int st = 128; st > 0; st >>= 1){
                if (t < st) red[t] += red[t + st];
                __syncthreads();
            }
            float C0 = red[0] + __ldcg(&g_B2);
            float totDA = DA[255], totDB = DB[255];

            float exUA = (t > 0) ? UA[t-1] : 0.f;
            float exUB = (t > 0) ? UB[t-1] : 0.f;
            float exDA = (t > 0) ? DA[t-1] : 0.f;
            float exDB = (t > 0) ? DB[t-1] : 0.f;

            g_T [i*256 + t] = key[t];
            g_Pa[i*257 + t] = exUA + (totDA - exDA);
            g_Pb[i*257 + t] = exUB + (totDB - exDB) + C0;
            if (t == 255){
                g_Pa[i*257 + 256] = UA[255];
                g_Pb[i*257 + 256] = UB[255] + C0;
            }
            __syncthreads();
        }

        // ---- gemm: 64 rows per CTA in two passes (math unchanged) ----
        for (int pp = 0; pp < 2; pp++){
            float* xs = dyn;                    // 16KB
            int n0 = bid*64 + pp*32;
            __syncthreads();
            for (int idx = t; idx < 32*128; idx += 256)
                xs[idx] = x[n0*128 + idx];
            __syncthreads();

            int i  = t & 127;
            int ng = t >> 7;
            const ulonglong2* wrow2 = (const ulonglong2*)(g_Wt + i*128);
            u64 acc[16];
            #pragma unroll
            for (int u = 0; u < 16; u++) acc[u] = 0ULL;

            #pragma unroll 4
            for (int q = 0; q < 32; q++){
                ulonglong2 wv = wrow2[q];
                u64 w01 = wv.x, w23 = wv.y;
                #pragma unroll
                for (int u = 0; u < 16; u++){
                    const u64* xp = (const u64*)&xs[(ng*16 + u)*128 + q*4];
                    acc[u] = fma2(xp[0], w01, acc[u]);
                    acc[u] = fma2(xp[1], w23, acc[u]);
                }
            }
            float bi = bias[i];
            #pragma unroll
            for (int u = 0; u < 16; u++){
                float p, q; upk2(acc[u], p, q);
                g_y[(n0 + ng*16 + u)*Dd + i] = (p + q) + bi;
            }
        }
        barX(&g_genC, g_leafC, &g_rootC, sid, 8, 8, 1);   // tables + y complete

        // ---- feval: tables once, 8 n-tiles of 128 rows ----
        {
            float* sT  = dyn;
            float* sPa = sT  + FEVAL_I*257;
            float* sPb = sPa + FEVAL_I*257;
            int i0 = (bid & 15) * FEVAL_I;

            for (int idx = t; idx < FEVAL_I*257; idx += 256){
                int ii = idx / 257, kk = idx - ii*257;
                sT [idx] = (kk < 256) ? __ldcg(&g_T[(i0+ii)*256 + kk])
                                      : __int_as_float(0x7f800000);
                sPa[idx] = __ldcg(&g_Pa[(i0+ii)*257 + kk]);
                sPb[idx] = __ldcg(&g_Pb[(i0+ii)*257 + kk]);
            }
            __syncthreads();

            int li = t & 7, rg = t >> 3;
            const float* Tl  = sT  + li*257;
            const float* Pal = sPa + li*257;
            const float* Pbl = sPb + li*257;

            #pragma unroll
            for (int q = 0; q < 8; q++){
                int n0 = (bid >> 4)*1024 + q*128;
                float yv[4];
                int   kk[4];
                #pragma unroll
                for (int p = 0; p < 4; p++){
                    yv[p] = __ldcg(&g_y[(n0 + rg + p*32)*Dd + i0 + li]);
                    kk[p] = 0;
                }
                #pragma unroll
                for (int stp = 128; stp > 0; stp >>= 1){
                    #pragma unroll
                    for (int p = 0; p < 4; p++)
                        if (Tl[kk[p] + stp - 1] < yv[p]) kk[p] += stp;
                }
                #pragma unroll
                for (int p = 0; p < 4; p++)
                    d_out[(n0 + rg + p*32)*Dd + i0 + li]
                        = fmaf(yv[p], Pal[kk[p]], Pbl[kk[p]]);
            }
        }
    } else {
        // ================= ladder squad: starts right after prep ===========
        float* Rt = dyn;                    // 128*128 floats
        float* Ls = dyn + 128*128;          // up to 512 floats
        int j = t & 127, h = t >> 7;
        for (int lv = 0; lv < 7; lv++){
            int two = g_lvl2[lv];
            const float* L; const float* R; float* Dm;
            int rbase;
            if (two){
                int p = (int)(sid >> 5);          // 32 CTAs per product
                rbase = (int)(sid & 31) * 4;      // 4 rows
                L = g_lvlL[lv*2 + p]; R = g_lvlR[lv*2 + p]; Dm = g_lvlD[lv*2 + p];
            } else {
                rbase = (int)sid * 2;             // 2 rows
                L = g_lvlL[lv*2]; R = g_lvlR[lv*2]; Dm = g_lvlD[lv*2];
            }

            // stage R row-major into smem (conflict-free float4 copy)
            {
                const float4* R4 = (const float4*)R;
                float4* S4 = (float4*)Rt;
                #pragma unroll
                for (int q = t; q < 4096; q += 256)
                    S4[q] = __ldcg(R4 + q);
            }
            if (two){
                Ls[t]       = __ldcg(L + rbase*128 + t);
                Ls[t + 256] = __ldcg(L + rbase*128 + t + 256);
            } else {
                Ls[t] = __ldcg(L + rbase*128 + t);
            }
            __syncthreads();

            const float* Rj = Rt + j;
            float buf[8];
            #pragma unroll
            for (int k = 0; k < 8; k++) buf[k] = Rj[k*128];

            if (two){
                const float* L0 = Ls + h*128;
                const float* L1 = L0 + 256;       // row +2
                float a0 = 0.f, a1 = 0.f;         // two single-acc chains
                #pragma unroll
                for (int k = 0; k < 120; k++){
                    float v = buf[k & 7];
                    buf[k & 7] = Rj[(k+8)*128];
                    a0 = fmaf(L0[k], v, a0);
                    a1 = fmaf(L1[k], v, a1);
                }
                #pragma unroll
                for (int k = 120; k < 128; k++){
                    float v = buf[k & 7];
                    a0 = fmaf(L0[k], v, a0);
                    a1 = fmaf(L1[k], v, a1);
                }
                Dm[(rbase + h)*128 + j]     = a0;
                Dm[(rbase + h + 2)*128 + j] = a1;
            } else {
                const float* L0 = Ls + h*128;
                float a0 = 0.f;                   // single-acc ascending-k
                #pragma unroll
                for (int k = 0; k < 120; k++){
                    float v = buf[k & 7];
                    buf[k & 7] = Rj[(k+8)*128];
                    a0 = fmaf(L0[k], v, a0);
                }
                #pragma unroll
                for (int k = 120; k < 128; k++)
                    a0 = fmaf(L0[k], buf[k & 7], a0);
                Dm[(rbase + h)*128 + j] = a0;
            }
            barX(&g_genL, g_leafL, &g_rootL, sid, 8, 8, (unsigned)(lv + 1));
        }

        // transpose P127 -> ET (2 columns per CTA)
        {
            int c  = (int)sid*2 + h;
            g_ET[c*128 + j] = __ldcg(&g_P127[j*128 + c]);
        }
    }
    barX(&g_genF, g_leafF, &g_rootF, (unsigned)bid, 16, 8, 2);

    // ---------- hsum (block 0; identical FMA order) -------------------------
    if (bid == 0){
        for (int q = t; q < 4096; q += 256){
            touch4((const float4*)g_ET + q);
            touch4((const float4*)g_M  + q);
        }
        __syncthreads();
        if (t < 32){
            __shared__ float pp[32];
            int l = t;
            float bufE[8], bufM[8];
            #pragma unroll
            for (int q = 0; q < 8; q++){
                int idx = l + (q << 5);
                bufE[q] = g_ET[idx];
                bufM[q] = g_M[idx];
            }
            float s = 0.f;
            for (int it = 0; it < 504; it++){
                float e = bufE[it & 7], m = bufM[it & 7];
                int idx = l + ((it + 8) << 5);
                bufE[it & 7] = g_ET[idx];
                bufM[it & 7] = g_M[idx];
                s = fmaf(e, m, s);
            }
            #pragma unroll
            for (int it = 504; it < 512; it++)
                s = fmaf(bufE[it & 7], bufM[it & 7], s);
            pp[l] = s;
            __syncwarp();
            for (int st = 16; st > 0; st >>= 1){
                if (l < st) pp[l] += pp[l + st];
                __syncwarp();
            }
            if (l == 0) d_out[Nn*Dd] = pp[0] - 128.f;
        }
    }
}

// ---------------- launch ------------------------------------------------------
extern "C" void kernel_launch(void* const* d_in, const int* in_sizes, int n_in,
                              void* d_out, int out_size)
{
    (void)in_sizes; (void)n_in; (void)out_size;
    const float* x      = (const float*)d_in[0];
    const float* weight = (const float*)d_in[1];
    const float* bias   = (const float*)d_in[2];
    const float* A      = (const float*)d_in[3];
    const float* W1     = (const float*)d_in[4];
    const float* b1     = (const float*)d_in[5];
    const float* W2     = (const float*)d_in[6];
    const float* b2     = (const float*)d_in[7];
    float* out = (float*)d_out;

    const int MEGA_SMEM = (128*128 + 512)*(int)sizeof(float);  // 67584

    static bool attr_done = false;
    if (!attr_done){
        cudaFuncSetAttribute(mega_kernel,
                             cudaFuncAttributeMaxDynamicSharedMemorySize, MEGA_SMEM);
        attr_done = true;
    }

    mega_kernel<<<128, 256, MEGA_SMEM>>>(x, weight, bias, A, W1, b1, W2, b2, out);
}

// round 16
// speedup vs baseline: 1.8701x; 1.0006x over previous
#include <cuda_runtime.h>

#define Nn 4096
#define Dd 128
#define H1h 256

typedef unsigned long long u64;

// ---------------- device scratch (all matrices 128B-aligned) ----------------
__device__ __align__(128) float g_Wt [Dd*Dd];
__device__ __align__(128) float g_M  [Dd*Dd];
__device__ __align__(128) float g_P2[Dd*Dd],  g_P3[Dd*Dd],  g_P4[Dd*Dd],  g_P7[Dd*Dd];
__device__ __align__(128) float g_P8[Dd*Dd],  g_P15[Dd*Dd], g_P16[Dd*Dd], g_P31[Dd*Dd];
__device__ __align__(128) float g_P32[Dd*Dd], g_P63[Dd*Dd], g_P64[Dd*Dd], g_P127[Dd*Dd];
__device__ __align__(128) float g_ET [Dd*Dd];
__device__ float g_s2[H1h];
__device__ float g_B2;
__device__ float g_regP[128];
__device__ __align__(128) float g_y [Nn*Dd];
__device__ float g_T [Dd*256];
__device__ float g_Pa[Dd*257];
__device__ float g_Pb[Dd*257];

// ladder level tables: [lv*2 + product]
__device__ float* const g_lvlL[14] = {g_M,g_M,  g_M,g_P2,  g_P3,g_P4,  g_P7,g_P8,
                                      g_P15,g_P16, g_P31,g_P32, g_P63,g_P63};
__device__ float* const g_lvlR[14] = {g_M,g_M,  g_P2,g_P2, g_P4,g_P4,  g_P8,g_P8,
                                      g_P16,g_P16, g_P32,g_P32, g_P64,g_P64};
__device__ float* const g_lvlD[14] = {g_P2,g_P2, g_P3,g_P4, g_P7,g_P8,  g_P15,g_P16,
                                      g_P31,g_P32, g_P63,g_P64, g_P127,g_P127};
__device__ const int g_lvl2[7] = {0,1,1,1,1,1,0};

// -------- three barrier objects: full(128), squadC(64), squadL(64) ----------
__device__ volatile unsigned g_genF = 0;
__device__ unsigned g_leafF[16*32];
__device__ unsigned g_rootF = 0;
__device__ volatile unsigned g_genC = 0;
__device__ unsigned g_leafC[8*32];
__device__ unsigned g_rootC = 0;
__device__ volatile unsigned g_genL = 0;
__device__ unsigned g_leafL[8*32];
__device__ unsigned g_rootL = 0;

// Tree barrier with absolute-target release (replay-safe).
__device__ __forceinline__ void barX(volatile unsigned* genp, unsigned* leaf,
                                     unsigned* root, unsigned sid,
                                     unsigned nleaf, unsigned perleaf,
                                     unsigned target){
    __syncthreads();
    if (threadIdx.x == 0){
        __threadfence();
        unsigned lf = sid & (nleaf - 1u);
        if (atomicAdd(&leaf[lf*32], 1u) == perleaf - 1u){
            leaf[lf*32] = 0;
            __threadfence();
            if (atomicAdd(root, 1u) == nleaf - 1u){
                *root = 0;
                __threadfence();
                *genp = target;
            }
        }
        while (*genp != target){
            #pragma unroll
            for (int q = 0; q < 40; q++) asm volatile("");
        }
    }
    __syncthreads();
}

// ---------------- helpers ----------------------------------------------------
__device__ __forceinline__ void upk2(u64 v, float& lo, float& hi){
    asm("mov.b64 {%0, %1}, %2;" : "=f"(lo), "=f"(hi) : "l"(v));
}
__device__ __forceinline__ u64 fma2(u64 a, u64 b, u64 c){
    u64 d; asm("fma.rn.f32x2 %0, %1, %2, %3;" : "=l"(d) : "l"(a), "l"(b), "l"(c));
    return d;
}
__device__ __forceinline__ void touch4(const float4* p){
    float a, b, c, d;
    asm volatile("ld.global.ca.v4.f32 {%0,%1,%2,%3}, [%4];"
                 : "=f"(a), "=f"(b), "=f"(c), "=f"(d) : "l"(p));
}

// ======== ONE kernel: prep, then {fsetup+gemm+feval} || {ladder}, hsum ======
#define FEVAL_I 8
__global__ void __launch_bounds__(256, 1)
mega_kernel(const float* __restrict__ x,
            const float* __restrict__ weight,
            const float* __restrict__ bias,
            const float* __restrict__ A,
            const float* __restrict__ W1,
            const float* __restrict__ b1,
            const float* __restrict__ W2,
            const float* __restrict__ b2,
            float* __restrict__ d_out)
{
    extern __shared__ __align__(16) float dyn[];   // 67584 B
    __shared__ float red[256];
    __shared__ float key[256]; __shared__ int sidx[256];
    __shared__ float asA[256], bsA[256];
    __shared__ int   upA[256];
    __shared__ float UA[256], UB[256], DA[256], DB[256];

    int t = threadIdx.x, bid = blockIdx.x;
    bool isC = (bid < 64);
    unsigned sid = isC ? (unsigned)bid : (unsigned)(bid - 64);

    // ---------- phase 0: prep (all 128 CTAs) -------------------------------
    {
        float labs = 0.f;
        if (t < 128){
            int idx = bid*128 + t;
            float w = weight[idx] * A[idx];
            int r = idx >> 7, c = idx & 127;
            g_Wt[c*Dd + r] = w;
            g_M[idx] = (r == c ? 1.f : 0.f) + (w*w)*(1.f/128.f);
            labs = fabsf(w);
        }
        {
            int w = t >> 5, lane = t & 31;
            if (w < 2){
                int row = bid*2 + w;
                const float* p = W2 + row*128;
                float v = (p[lane] + p[lane+32]) + (p[lane+64] + p[lane+96]);
                #pragma unroll
                for (int s = 16; s > 0; s >>= 1)
                    v += __shfl_xor_sync(0xffffffffu, v, s);
                if (lane == 0) g_s2[row] = v;
            }
        }
        if (bid == 0){
            red[t] = (t < 128) ? b2[t] : 0.f;
            __syncthreads();
            for (int s = 128; s > 0; s >>= 1){
                if (t < s) red[t] += red[t + s];
                __syncthreads();
            }
            if (t == 0) g_B2 = red[0];
            __syncthreads();
        }
        red[t] = labs;
        __syncthreads();
        for (int s = 128; s > 0; s >>= 1){
            if (t < s) red[t] += red[t + s];
            __syncthreads();
        }
        if (t == 0) g_regP[bid] = red[0];
    }
    barX(&g_genF, g_leafF, &g_rootF, (unsigned)bid, 16, 8, 1);

    if (isC){
        // ============ compute squad: reg-final, fsetup x2, gemm, feval ======
        if (bid == 0){
            red[t] = (t < 128) ? g_regP[t] : 0.f;
            __syncthreads();
            for (int s = 128; s > 0; s >>= 1){
                if (t < s) red[t] += red[t + s];
                __syncthreads();
            }
            if (t == 0) d_out[Nn*Dd + 1] = red[0];
        }
        __syncthreads();

        // ---- fsetup: columns 2*sid and 2*sid+1 (same per-column math) ----
        for (int ii = 0; ii < 2; ii++){
            int i = (int)sid*2 + ii;
            float a = W1[i*H1h + t];
            float bb = b1[t];
            float s = __ldcg(&g_s2[t]);
            float as = a*s, bs = bb*s;
            float tb; int up; float c0 = 0.f;
            if (a > 0.f)      { tb = -bb/a; up = 1; }
            else if (a < 0.f) { tb = -bb/a; up = 0; }
            else { tb = __int_as_float(0x7f800000); up = 1; as = 0.f; bs = 0.f;
                   c0 = fmaxf(bb, 0.f) * s; }

            key[t] = tb; sidx[t] = t;
            asA[t] = as; bsA[t] = bs; upA[t] = up;
            __syncthreads();

            for (int ksz = 2; ksz <= 256; ksz <<= 1){
                for (int jsz = ksz >> 1; jsz > 0; jsz >>= 1){
                    int ixj = t ^ jsz;
                    float k0 = key[t], k1 = key[ixj];
                    int   i0 = sidx[t], i1 = sidx[ixj];
                    __syncthreads();
                    if (ixj > t){
                        bool asc = ((t & ksz) == 0);
                        bool sw  = asc ? (k0 > k1) : (k0 < k1);
                        if (sw){ key[t] = k1; key[ixj] = k0;
                                 sidx[t] = i1; sidx[ixj] = i0; }
                    }
                    __syncthreads();
                }
            }

            int o = sidx[t];
            float pas = asA[o], pbs = bsA[o];
            int pup = upA[o];
            UA[t] = pup ? pas : 0.f;  UB[t] = pup ? pbs : 0.f;
            DA[t] = pup ? 0.f : pas;  DB[t] = pup ? 0.f : pbs;
            __syncthreads();

            for (int off = 1; off < 256; off <<= 1){
                float ua = (t >= off) ? UA[t-off] : 0.f;
                float ub = (t >= off) ? UB[t-off] : 0.f;
                float da = (t >= off) ? DA[t-off] : 0.f;
                float db = (t >= off) ? DB[t-off] : 0.f;
                __syncthreads();
                UA[t] += ua; UB[t] += ub; DA[t] += da; DB[t] += db;
                __syncthreads();
            }

            red[t] = c0;
            __syncthreads();
            for (int st = 128; st > 0; st >>= 1){
                if (t < st) red[t] += red[t + st];
                __syncthreads();
            }
            float C0 = red[0] + __ldcg(&g_B2);
            float totDA = DA[255], totDB = DB[255];

            float exUA = (t > 0) ? UA[t-1] : 0.f;
            float exUB = (t > 0) ? UB[t-1] : 0.f;
            float exDA = (t > 0) ? DA[t-1] : 0.f;
            float exDB = (t > 0) ? DB[t-1] : 0.f;

            g_T [i*256 + t] = key[t];
            g_Pa[i*257 + t] = exUA + (totDA - exDA);
            g_Pb[i*257 + t] = exUB + (totDB - exDB) + C0;
            if (t == 255){
                g_Pa[i*257 + 256] = UA[255];
                g_Pb[i*257 + 256] = UB[255] + C0;
            }
            __syncthreads();
        }

        // ---- gemm: 64 rows per CTA in two passes (math unchanged) ----
        for (int pp = 0; pp < 2; pp++){
            float* xs = dyn;                    // 16KB
            int n0 = bid*64 + pp*32;
            __syncthreads();
            for (int idx = t; idx < 32*128; idx += 256)
                xs[idx] = x[n0*128 + idx];
            __syncthreads();

            int i  = t & 127;
            int ng = t >> 7;
            const ulonglong2* wrow2 = (const ulonglong2*)(g_Wt + i*128);
            u64 acc[16];
            #pragma unroll
            for (int u = 0; u < 16; u++) acc[u] = 0ULL;

            #pragma unroll 4
            for (int q = 0; q < 32; q++){
                ulonglong2 wv = wrow2[q];
                u64 w01 = wv.x, w23 = wv.y;
                #pragma unroll
                for (int u = 0; u < 16; u++){
                    const u64* xp = (const u64*)&xs[(ng*16 + u)*128 + q*4];
                    acc[u] = fma2(xp[0], w01, acc[u]);
                    acc[u] = fma2(xp[1], w23, acc[u]);
                }
            }
            float bi = bias[i];
            #pragma unroll
            for (int u = 0; u < 16; u++){
                float p, q; upk2(acc[u], p, q);
                g_y[(n0 + ng*16 + u)*Dd + i] = (p + q) + bi;
            }
        }
        barX(&g_genC, g_leafC, &g_rootC, sid, 8, 8, 1);   // tables + y complete

        // ---- feval: tables once, 8 n-tiles of 128 rows ----
        {
            float* sT  = dyn;
            float* sPa = sT  + FEVAL_I*257;
            float* sPb = sPa + FEVAL_I*257;
            int i0 = (bid & 15) * FEVAL_I;

            for (int idx = t; idx < FEVAL_I*257; idx += 256){
                int ii = idx / 257, kk = idx - ii*257;
                sT [idx] = (kk < 256) ? __ldcg(&g_T[(i0+ii)*256 + kk])
                                      : __int_as_float(0x7f800000);
                sPa[idx] = __ldcg(&g_Pa[(i0+ii)*257 + kk]);
                sPb[idx] = __ldcg(&g_Pb[(i0+ii)*257 + kk]);
            }
            __syncthreads();

            int li = t & 7, rg = t >> 3;
            const float* Tl  = sT  + li*257;
            const float* Pal = sPa + li*257;
            const float* Pbl = sPb + li*257;

            #pragma unroll
            for (int q = 0; q < 8; q++){
                int n0 = (bid >> 4)*1024 + q*128;
                float yv[4];
                int   kk[4];
                #pragma unroll
                for (int p = 0; p < 4; p++){
                    yv[p] = __ldcg(&g_y[(n0 + rg + p*32)*Dd + i0 + li]);
                    kk[p] = 0;
                }
                #pragma unroll
                for (int stp = 128; stp > 0; stp >>= 1){
                    #pragma unroll
                    for (int p = 0; p < 4; p++)
                        if (Tl[kk[p] + stp - 1] < yv[p]) kk[p] += stp;
                }
                #pragma unroll
                for (int p = 0; p < 4; p++)
                    d_out[(n0 + rg + p*32)*Dd + i0 + li]
                        = fmaf(yv[p], Pal[kk[p]], Pbl[kk[p]]);
            }
        }
    } else {
        // ================= ladder squad: starts right after prep ===========
        float* Rt = dyn;                    // 128*128 floats
        float* Ls = dyn + 128*128;          // up to 512 floats
        int j = t & 127, h = t >> 7;
        for (int lv = 0; lv < 7; lv++){
            int two = g_lvl2[lv];
            const float* L; const float* R; float* Dm;
            int rbase;
            if (two){
                int p = (int)(sid >> 5);          // 32 CTAs per product
                rbase = (int)(sid & 31) * 4;      // 4 rows
                L = g_lvlL[lv*2 + p]; R = g_lvlR[lv*2 + p]; Dm = g_lvlD[lv*2 + p];
            } else {
                rbase = (int)sid * 2;             // 2 rows
                L = g_lvlL[lv*2]; R = g_lvlR[lv*2]; Dm = g_lvlD[lv*2];
            }

            // stage R row-major into smem (conflict-free float4 copy)
            {
                const float4* R4 = (const float4*)R;
                float4* S4 = (float4*)Rt;
                #pragma unroll
                for (int q = t; q < 4096; q += 256)
                    S4[q] = __ldcg(R4 + q);
            }
            if (two){
                Ls[t]       = __ldcg(L + rbase*128 + t);
                Ls[t + 256] = __ldcg(L + rbase*128 + t + 256);
            } else {
                Ls[t] = __ldcg(L + rbase*128 + t);
            }
            __syncthreads();

            const float* Rj = Rt + j;
            float buf[8];
            #pragma unroll
            for (int k = 0; k < 8; k++) buf[k] = Rj[k*128];

            if (two){
                const float* L0 = Ls + h*128;
                const float* L1 = L0 + 256;       // row +2
                float a0 = 0.f, a1 = 0.f;         // two single-acc chains
                #pragma unroll
                for (int k = 0; k < 120; k++){
                    float v = buf[k & 7];
                    buf[k & 7] = Rj[(k+8)*128];
                    a0 = fmaf(L0[k], v, a0);
                    a1 = fmaf(L1[k], v, a1);
                }
                #pragma unroll
                for (int k = 120; k < 128; k++){
                    float v = buf[k & 7];
                    a0 = fmaf(L0[k], v, a0);
                    a1 = fmaf(L1[k], v, a1);
                }
                Dm[(rbase + h)*128 + j]     = a0;
                Dm[(rbase + h + 2)*128 + j] = a1;
            } else {
                const float* L0 = Ls + h*128;
                float a0 = 0.f;                   // single-acc ascending-k
                #pragma unroll
                for (int k = 0; k < 120; k++){
                    float v = buf[k & 7];
                    buf[k & 7] = Rj[(k+8)*128];
                    a0 = fmaf(L0[k], v, a0);
                }
                #pragma unroll
                for (int k = 120; k < 128; k++)
                    a0 = fmaf(L0[k], buf[k & 7], a0);
                Dm[(rbase + h)*128 + j] = a0;
            }
            barX(&g_genL, g_leafL, &g_rootL, sid, 8, 8, (unsigned)(lv + 1));
        }

        // transpose P127 -> ET (2 columns per CTA)
        {
            int c  = (int)sid*2 + h;
            g_ET[c*128 + j] = __ldcg(&g_P127[j*128 + c]);
        }
    }
    barX(&g_genF, g_leafF, &g_rootF, (unsigned)bid, 16, 8, 2);

    // ---------- hsum (block 0; identical FMA order) -------------------------
    if (bid == 0){
        for (int q = t; q < 4096; q += 256){
            touch4((const float4*)g_ET + q);
            touch4((const float4*)g_M  + q);
        }
        __syncthreads();
        if (t < 32){
            __shared__ float pp[32];
            int l = t;
            float bufE[8], bufM[8];
            #pragma unroll
            for (int q = 0; q < 8; q++){
                int idx = l + (q << 5);
                bufE[q] = g_ET[idx];
                bufM[q] = g_M[idx];
            }
            float s = 0.f;
            for (int it = 0; it < 504; it++){
                float e = bufE[it & 7], m = bufM[it & 7];
                int idx = l + ((it + 8) << 5);
                bufE[it & 7] = g_ET[idx];
                bufM[it & 7] = g_M[idx];
                s = fmaf(e, m, s);
            }
            #pragma unroll
            for (int it = 504; it < 512; it++)
                s = fmaf(bufE[it & 7], bufM[it & 7], s);
            pp[l] = s;
            __syncwarp();
            for (int st = 16; st > 0; st >>= 1){
                if (l < st) pp[l] += pp[l + st];
                __syncwarp();
            }
            if (l == 0) d_out[Nn*Dd] = pp[0] - 128.f;
        }
    }
}

// ---------------- launch ------------------------------------------------------
extern "C" void kernel_launch(void* const* d_in, const int* in_sizes, int n_in,
                              void* d_out, int out_size)
{
    (void)in_sizes; (void)n_in; (void)out_size;
    const float* x      = (const float*)d_in[0];
    const float* weight = (const float*)d_in[1];
    const float* bias   = (const float*)d_in[2];
    const float* A      = (const float*)d_in[3];
    const float* W1     = (const float*)d_in[4];
    const float* b1     = (const float*)d_in[5];
    const float* W2     = (const float*)d_in[6];
    const float* b2     = (const float*)d_in[7];
    float* out = (float*)d_out;

    const int MEGA_SMEM = (128*128 + 512)*(int)sizeof(float);  // 67584

    static bool attr_done = false;
    if (!attr_done){
        cudaFuncSetAttribute(mega_kernel,
                             cudaFuncAttributeMaxDynamicSharedMemorySize, MEGA_SMEM);
        attr_done = true;
    }

    mega_kernel<<<128, 256, MEGA_SMEM>>>(x, weight, bias, A, W1, b1, W2, b2, out);
}

// round 17
// speedup vs baseline: 1.9418x; 1.0384x over previous
#include <cuda_runtime.h>

#define Nn 4096
#define Dd 128
#define H1h 256

typedef unsigned long long u64;

// ---------------- device scratch (all matrices 128B-aligned) ----------------
__device__ __align__(128) float g_Wt [Dd*Dd];
__device__ __align__(128) float g_M  [Dd*Dd];
__device__ __align__(128) float g_P2[Dd*Dd],  g_P3[Dd*Dd],  g_P4[Dd*Dd],  g_P7[Dd*Dd];
__device__ __align__(128) float g_P8[Dd*Dd],  g_P15[Dd*Dd], g_P16[Dd*Dd], g_P31[Dd*Dd];
__device__ __align__(128) float g_P32[Dd*Dd], g_P63[Dd*Dd], g_P64[Dd*Dd], g_P127[Dd*Dd];
__device__ __align__(128) float g_ET [Dd*Dd];
__device__ float g_s2[H1h];
__device__ float g_B2;
__device__ float g_regP[128];
__device__ __align__(128) float g_y [Nn*Dd];
__device__ float g_T [Dd*256];
__device__ float g_Pa[Dd*257];
__device__ float g_Pb[Dd*257];

// ladder level tables: [lv*2 + product]
__device__ float* const g_lvlL[14] = {g_M,g_M,  g_M,g_P2,  g_P3,g_P4,  g_P7,g_P8,
                                      g_P15,g_P16, g_P31,g_P32, g_P63,g_P63};
__device__ float* const g_lvlR[14] = {g_M,g_M,  g_P2,g_P2, g_P4,g_P4,  g_P8,g_P8,
                                      g_P16,g_P16, g_P32,g_P32, g_P64,g_P64};
__device__ float* const g_lvlD[14] = {g_P2,g_P2, g_P3,g_P4, g_P7,g_P8,  g_P15,g_P16,
                                      g_P31,g_P32, g_P63,g_P64, g_P127,g_P127};
__device__ const int g_lvl2[7] = {0,1,1,1,1,1,0};

// -------- three barrier objects: full(128), squadC(64), squadL(64) ----------
__device__ volatile unsigned g_genF = 0;
__device__ unsigned g_leafF[16*32];
__device__ unsigned g_rootF = 0;
__device__ volatile unsigned g_genC = 0;
__device__ unsigned g_leafC[8*32];
__device__ unsigned g_rootC = 0;
__device__ volatile unsigned g_genL = 0;
__device__ unsigned g_leafL[8*32];
__device__ unsigned g_rootL = 0;

// Tree barrier with absolute-target release (replay-safe).
__device__ __forceinline__ void barX(volatile unsigned* genp, unsigned* leaf,
                                     unsigned* root, unsigned sid,
                                     unsigned nleaf, unsigned perleaf,
                                     unsigned target){
    __syncthreads();
    if (threadIdx.x == 0){
        __threadfence();
        unsigned lf = sid & (nleaf - 1u);
        if (atomicAdd(&leaf[lf*32], 1u) == perleaf - 1u){
            leaf[lf*32] = 0;
            __threadfence();
            if (atomicAdd(root, 1u) == nleaf - 1u){
                *root = 0;
                __threadfence();
                *genp = target;
            }
        }
        while (*genp != target){
            #pragma unroll
            for (int q = 0; q < 40; q++) asm volatile("");
        }
    }
    __syncthreads();
}

// ---------------- helpers ----------------------------------------------------
__device__ __forceinline__ void upk2(u64 v, float& lo, float& hi){
    asm("mov.b64 {%0, %1}, %2;" : "=f"(lo), "=f"(hi) : "l"(v));
}
__device__ __forceinline__ u64 fma2(u64 a, u64 b, u64 c){
    u64 d; asm("fma.rn.f32x2 %0, %1, %2, %3;" : "=l"(d) : "l"(a), "l"(b), "l"(c));
    return d;
}
__device__ __forceinline__ void touch4(const float4* p){
    float a, b, c, d;
    asm volatile("ld.global.ca.v4.f32 {%0,%1,%2,%3}, [%4];"
                 : "=f"(a), "=f"(b), "=f"(c), "=f"(d) : "l"(p));
}

// ======== ONE kernel: prep, then {fsetup+gemm+feval} || {ladder}, hsum ======
#define FEVAL_I 8
__global__ void __launch_bounds__(256, 1)
mega_kernel(const float* __restrict__ x,
            const float* __restrict__ weight,
            const float* __restrict__ bias,
            const float* __restrict__ A,
            const float* __restrict__ W1,
            const float* __restrict__ b1,
            const float* __restrict__ W2,
            const float* __restrict__ b2,
            float* __restrict__ d_out)
{
    extern __shared__ __align__(16) float dyn[];   // 67584 B
    __shared__ float red[256];
    __shared__ float key[256]; __shared__ int sidx[256];
    __shared__ float asA[256], bsA[256];
    __shared__ int   upA[256];
    __shared__ float UA[256], UB[256], DA[256], DB[256];

    int t = threadIdx.x, bid = blockIdx.x;
    bool isC = (bid < 64);
    unsigned sid = isC ? (unsigned)bid : (unsigned)(bid - 64);

    // ---------- phase 0: prep (all 128 CTAs) -------------------------------
    {
        float labs = 0.f;
        if (t < 128){
            int idx = bid*128 + t;
            float w = weight[idx] * A[idx];
            int r = idx >> 7, c = idx & 127;
            g_Wt[c*Dd + r] = w;
            g_M[idx] = (r == c ? 1.f : 0.f) + (w*w)*(1.f/128.f);
            labs = fabsf(w);
        }
        {
            int w = t >> 5, lane = t & 31;
            if (w < 2){
                int row = bid*2 + w;
                const float* p = W2 + row*128;
                float v = (p[lane] + p[lane+32]) + (p[lane+64] + p[lane+96]);
                #pragma unroll
                for (int s = 16; s > 0; s >>= 1)
                    v += __shfl_xor_sync(0xffffffffu, v, s);
                if (lane == 0) g_s2[row] = v;
            }
        }
        if (bid == 0){
            red[t] = (t < 128) ? b2[t] : 0.f;
            __syncthreads();
            for (int s = 128; s > 0; s >>= 1){
                if (t < s) red[t] += red[t + s];
                __syncthreads();
            }
            if (t == 0) g_B2 = red[0];
            __syncthreads();
        }
        red[t] = labs;
        __syncthreads();
        for (int s = 128; s > 0; s >>= 1){
            if (t < s) red[t] += red[t + s];
            __syncthreads();
        }
        if (t == 0) g_regP[bid] = red[0];
    }
    barX(&g_genF, g_leafF, &g_rootF, (unsigned)bid, 16, 8, 1);

    if (isC){
        // ============ compute squad: reg-final, fsetup x2, gemm, feval ======
        if (bid == 0){
            red[t] = (t < 128) ? g_regP[t] : 0.f;
            __syncthreads();
            for (int s = 128; s > 0; s >>= 1){
                if (t < s) red[t] += red[t + s];
                __syncthreads();
            }
            if (t == 0) d_out[Nn*Dd + 1] = red[0];
        }
        __syncthreads();

        // ---- fsetup: columns 2*sid and 2*sid+1 (same per-column math) ----
        for (int ii = 0; ii < 2; ii++){
            int i = (int)sid*2 + ii;
            float a = W1[i*H1h + t];
            float bb = b1[t];
            float s = __ldcg(&g_s2[t]);
            float as = a*s, bs = bb*s;
            float tb; int up; float c0 = 0.f;
            if (a > 0.f)      { tb = -bb/a; up = 1; }
            else if (a < 0.f) { tb = -bb/a; up = 0; }
            else { tb = __int_as_float(0x7f800000); up = 1; as = 0.f; bs = 0.f;
                   c0 = fmaxf(bb, 0.f) * s; }

            key[t] = tb; sidx[t] = t;
            asA[t] = as; bsA[t] = bs; upA[t] = up;
            __syncthreads();

            for (int ksz = 2; ksz <= 256; ksz <<= 1){
                for (int jsz = ksz >> 1; jsz > 0; jsz >>= 1){
                    int ixj = t ^ jsz;
                    float k0 = key[t], k1 = key[ixj];
                    int   i0 = sidx[t], i1 = sidx[ixj];
                    __syncthreads();
                    if (ixj > t){
                        bool asc = ((t & ksz) == 0);
                        bool sw  = asc ? (k0 > k1) : (k0 < k1);
                        if (sw){ key[t] = k1; key[ixj] = k0;
                                 sidx[t] = i1; sidx[ixj] = i0; }
                    }
                    __syncthreads();
                }
            }

            int o = sidx[t];
            float pas = asA[o], pbs = bsA[o];
            int pup = upA[o];
            UA[t] = pup ? pas : 0.f;  UB[t] = pup ? pbs : 0.f;
            DA[t] = pup ? 0.f : pas;  DB[t] = pup ? 0.f : pbs;
            __syncthreads();

            for (int off = 1; off < 256; off <<= 1){
                float ua = (t >= off) ? UA[t-off] : 0.f;
                float ub = (t >= off) ? UB[t-off] : 0.f;
                float da = (t >= off) ? DA[t-off] : 0.f;
                float db = (t >= off) ? DB[t-off] : 0.f;
                __syncthreads();
                UA[t] += ua; UB[t] += ub; DA[t] += da; DB[t] += db;
                __syncthreads();
            }

            red[t] = c0;
            __syncthreads();
            for (int st = 128; st > 0; st >>= 1){
                if (t < st) red[t] += red[t + st];
                __syncthreads();
            }
            float C0 = red[0] + __ldcg(&g_B2);
            float totDA = DA[255], totDB = DB[255];

            float exUA = (t > 0) ? UA[t-1] : 0.f;
            float exUB = (t > 0) ? UB[t-1] : 0.f;
            float exDA = (t > 0) ? DA[t-1] : 0.f;
            float exDB = (t > 0) ? DB[t-1] : 0.f;

            g_T [i*256 + t] = key[t];
            g_Pa[i*257 + t] = exUA + (totDA - exDA);
            g_Pb[i*257 + t] = exUB + (totDB - exDB) + C0;
            if (t == 255){
                g_Pa[i*257 + 256] = UA[255];
                g_Pb[i*257 + 256] = UB[255] + C0;
            }
            __syncthreads();
        }

        // ---- gemm: 64 rows per CTA in two passes (math unchanged) ----
        for (int pp = 0; pp < 2; pp++){
            float* xs = dyn;                    // 16KB
            int n0 = bid*64 + pp*32;
            __syncthreads();
            for (int idx = t; idx < 32*128; idx += 256)
                xs[idx] = x[n0*128 + idx];
            __syncthreads();

            int i  = t & 127;
            int ng = t >> 7;
            const ulonglong2* wrow2 = (const ulonglong2*)(g_Wt + i*128);
            u64 acc[16];
            #pragma unroll
            for (int u = 0; u < 16; u++) acc[u] = 0ULL;

            #pragma unroll 4
            for (int q = 0; q < 32; q++){
                ulonglong2 wv = wrow2[q];
                u64 w01 = wv.x, w23 = wv.y;
                #pragma unroll
                for (int u = 0; u < 16; u++){
                    const u64* xp = (const u64*)&xs[(ng*16 + u)*128 + q*4];
                    acc[u] = fma2(xp[0], w01, acc[u]);
                    acc[u] = fma2(xp[1], w23, acc[u]);
                }
            }
            float bi = bias[i];
            #pragma unroll
            for (int u = 0; u < 16; u++){
                float p, q; upk2(acc[u], p, q);
                g_y[(n0 + ng*16 + u)*Dd + i] = (p + q) + bi;
            }
        }
        barX(&g_genC, g_leafC, &g_rootC, sid, 8, 8, 1);   // tables + y complete

        // ---- feval: tables once, 8 n-tiles of 128 rows ----
        {
            float* sT  = dyn;
            float* sPa = sT  + FEVAL_I*257;
            float* sPb = sPa + FEVAL_I*257;
            int i0 = (bid & 15) * FEVAL_I;

            for (int idx = t; idx < FEVAL_I*257; idx += 256){
                int ii = idx / 257, kk = idx - ii*257;
                sT [idx] = (kk < 256) ? __ldcg(&g_T[(i0+ii)*256 + kk])
                                      : __int_as_float(0x7f800000);
                sPa[idx] = __ldcg(&g_Pa[(i0+ii)*257 + kk]);
                sPb[idx] = __ldcg(&g_Pb[(i0+ii)*257 + kk]);
            }
            __syncthreads();

            int li = t & 7, rg = t >> 3;
            const float* Tl  = sT  + li*257;
            const float* Pal = sPa + li*257;
            const float* Pbl = sPb + li*257;

            #pragma unroll
            for (int q = 0; q < 8; q++){
                int n0 = (bid >> 4)*1024 + q*128;
                float yv[4];
                int   kk[4];
                #pragma unroll
                for (int p = 0; p < 4; p++){
                    yv[p] = __ldcg(&g_y[(n0 + rg + p*32)*Dd + i0 + li]);
                    kk[p] = 0;
                }
                #pragma unroll
                for (int stp = 128; stp > 0; stp >>= 1){
                    #pragma unroll
                    for (int p = 0; p < 4; p++)
                        if (Tl[kk[p] + stp - 1] < yv[p]) kk[p] += stp;
                }
                #pragma unroll
                for (int p = 0; p < 4; p++)
                    d_out[(n0 + rg + p*32)*Dd + i0 + li]
                        = fmaf(yv[p], Pal[kk[p]], Pbl[kk[p]]);
            }
        }
    } else {
        // ================= ladder squad: starts right after prep ===========
        float* Rt = dyn;                    // 128*128 floats
        float* Ls = dyn + 128*128;          // up to 512 floats
        int j = t & 127, h = t >> 7;
        for (int lv = 0; lv < 7; lv++){
            int two = g_lvl2[lv];
            const float* L; const float* R; float* Dm;
            int rbase;
            if (two){
                int p = (int)(sid >> 5);          // 32 CTAs per product
                rbase = (int)(sid & 31) * 4;      // 4 rows
                L = g_lvlL[lv*2 + p]; R = g_lvlR[lv*2 + p]; Dm = g_lvlD[lv*2 + p];
            } else {
                rbase = (int)sid * 2;             // 2 rows
                L = g_lvlL[lv*2]; R = g_lvlR[lv*2]; Dm = g_lvlD[lv*2];
            }

            // stage R row-major into smem (conflict-free float4 copy)
            {
                const float4* R4 = (const float4*)R;
                float4* S4 = (float4*)Rt;
                #pragma unroll
                for (int q = t; q < 4096; q += 256)
                    S4[q] = __ldcg(R4 + q);
            }
            if (two){
                Ls[t]       = __ldcg(L + rbase*128 + t);
                Ls[t + 256] = __ldcg(L + rbase*128 + t + 256);
            } else {
                Ls[t] = __ldcg(L + rbase*128 + t);
            }
            __syncthreads();

            const float* Rj = Rt + j;
            float buf[8];
            #pragma unroll
            for (int k = 0; k < 8; k++) buf[k] = Rj[k*128];

            if (two){
                const float* L0 = Ls + h*128;
                const float* L1 = L0 + 256;       // row +2
                float a0 = 0.f, a1 = 0.f;         // two single-acc chains
                #pragma unroll
                for (int k = 0; k < 120; k++){
                    float v = buf[k & 7];
                    buf[k & 7] = Rj[(k+8)*128];
                    a0 = fmaf(L0[k], v, a0);
                    a1 = fmaf(L1[k], v, a1);
                }
                #pragma unroll
                for (int k = 120; k < 128; k++){
                    float v = buf[k & 7];
                    a0 = fmaf(L0[k], v, a0);
                    a1 = fmaf(L1[k], v, a1);
                }
                Dm[(rbase + h)*128 + j]     = a0;
                Dm[(rbase + h + 2)*128 + j] = a1;
            } else {
                const float* L0 = Ls + h*128;
                float a0 = 0.f;                   // single-acc ascending-k
                #pragma unroll
                for (int k = 0; k < 120; k++){
                    float v = buf[k & 7];
                    buf[k & 7] = Rj[(k+8)*128];
                    a0 = fmaf(L0[k], v, a0);
                }
                #pragma unroll
                for (int k = 120; k < 128; k++)
                    a0 = fmaf(L0[k], buf[k & 7], a0);
                Dm[(rbase + h)*128 + j] = a0;
            }
            barX(&g_genL, g_leafL, &g_rootL, sid, 8, 8, (unsigned)(lv + 1));
        }

        // transpose P127 -> ET (2 columns per CTA)
        {
            int c  = (int)sid*2 + h;
            g_ET[c*128 + j] = __ldcg(&g_P127[j*128 + c]);
        }
    }
    barX(&g_genF, g_leafF, &g_rootF, (unsigned)bid, 16, 8, 2);

    // ---------- hsum (block 0; identical FMA order) -------------------------
    if (bid == 0){
        for (int q = t; q < 4096; q += 256){
            touch4((const float4*)g_ET + q);
            touch4((const float4*)g_M  + q);
        }
        __syncthreads();
        if (t < 32){
            __shared__ float pp[32];
            int l = t;
            float bufE[8], bufM[8];
            #pragma unroll
            for (int q = 0; q < 8; q++){
                int idx = l + (q << 5);
                bufE[q] = g_ET[idx];
                bufM[q] = g_M[idx];
            }
            float s = 0.f;
            for (int it = 0; it < 504; it++){
                float e = bufE[it & 7], m = bufM[it & 7];
                int idx = l + ((it + 8) << 5);
                bufE[it & 7] = g_ET[idx];
                bufM[it & 7] = g_M[idx];
                s = fmaf(e, m, s);
            }
            #pragma unroll
            for (int it = 504; it < 512; it++)
                s = fmaf(bufE[it & 7], bufM[it & 7], s);
            pp[l] = s;
            __syncwarp();
            for (int st = 16; st > 0; st >>= 1){
                if (l < st) pp[l] += pp[l + st];
                __syncwarp();
            }
            if (l == 0) d_out[Nn*Dd] = pp[0] - 128.f;
        }
    }
}

// ---------------- launch ------------------------------------------------------
extern "C" void kernel_launch(void* const* d_in, const int* in_sizes, int n_in,
                              void* d_out, int out_size)
{
    (void)in_sizes; (void)n_in; (void)out_size;
    const float* x      = (const float*)d_in[0];
    const float* weight = (const float*)d_in[1];
    const float* bias   = (const float*)d_in[2];
    const float* A      = (const float*)d_in[3];
    const float* W1     = (const float*)d_in[4];
    const float* b1     = (const float*)d_in[5];
    const float* W2     = (const float*)d_in[6];
    const float* b2     = (const float*)d_in[7];
    float* out = (float*)d_out;

    const int MEGA_SMEM = (128*128 + 512)*(int)sizeof(float);  // 67584

    static bool attr_done = false;
    if (!attr_done){
        cudaFuncSetAttribute(mega_kernel,
                             cudaFuncAttributeMaxDynamicSharedMemorySize, MEGA_SMEM);
        attr_done = true;
    }

    mega_kernel<<<128, 256, MEGA_SMEM>>>(x, weight, bias, A, W1, b1, W2, b2, out);
}